// round 12
// baseline (speedup 1.0000x reference)
#include <cuda_runtime.h>
#include <cuda_fp16.h>
#include <math.h>
#include <stdint.h>

#define N_NODES 65536
#define EMBED 512
#define FFDIM 2048
#define QKVDIM 1536
#define NHEADS 8
#define HDIM 64

// ---------------- scratch ----------------------------------------------------
__device__ __half g_h[(size_t)N_NODES * EMBED];
__device__ __half g_qkv[(size_t)N_NODES * QKVDIM];
__device__ __half g_attnh[(size_t)N_NODES * EMBED];
__device__ __half g_x1h[(size_t)N_NODES * EMBED];
__device__ __half g_ffh[(size_t)N_NODES * FFDIM];
__device__ __half g_wqkv[QKVDIM * EMBED];
__device__ float  g_bqkv[QKVDIM];
__device__ __half g_wo[EMBED * EMBED];
__device__ __half g_w1[FFDIM * EMBED];
__device__ __half g_w2[EMBED * FFDIM];

// ---------------- ptx helpers ------------------------------------------------
__device__ __forceinline__ uint32_t smem_u32(const void* p) {
    uint32_t a;
    asm("{ .reg .u64 t; cvta.to.shared.u64 t, %1; cvt.u32.u64 %0, t; }" : "=r"(a) : "l"(p));
    return a;
}
__device__ __forceinline__ void cp_async16(uint32_t saddr, const void* gaddr) {
    asm volatile("cp.async.cg.shared.global [%0], [%1], 16;\n" :: "r"(saddr), "l"(gaddr));
}
__device__ __forceinline__ void cpasync_mbar_arrive(uint32_t mbar) {
    asm volatile("cp.async.mbarrier.arrive.noinc.shared.b64 [%0];" :: "r"(mbar) : "memory");
}
__device__ __forceinline__ void mbar_init(uint32_t mbar, uint32_t cnt) {
    asm volatile("mbarrier.init.shared.b64 [%0], %1;" :: "r"(mbar), "r"(cnt) : "memory");
}
__device__ __forceinline__ void mbar_arrive(uint32_t mbar) {
    asm volatile("mbarrier.arrive.shared.b64 _, [%0];" :: "r"(mbar) : "memory");
}
__device__ __forceinline__ void mbar_wait(uint32_t mbar, uint32_t parity) {
    asm volatile(
        "{\n\t.reg .pred P;\n\t"
        "WL%=:\n\t"
        "mbarrier.try_wait.parity.acquire.cta.shared::cta.b64 P, [%0], %1, 0x989680;\n\t"
        "@P bra WD%=;\n\t"
        "bra WL%=;\n\t"
        "WD%=:\n\t}"
        :: "r"(mbar), "r"(parity) : "memory");
}
__device__ __forceinline__ void ldm_x4(uint32_t* r, uint32_t addr) {
    asm volatile("ldmatrix.sync.aligned.m8n8.x4.shared.b16 {%0,%1,%2,%3}, [%4];"
                 : "=r"(r[0]), "=r"(r[1]), "=r"(r[2]), "=r"(r[3]) : "r"(addr));
}
__device__ __forceinline__ void mma16816(float* d, const uint32_t* a, const uint32_t* b) {
    asm volatile(
        "mma.sync.aligned.m16n8k16.row.col.f32.f16.f16.f32 "
        "{%0,%1,%2,%3}, {%4,%5,%6,%7}, {%8,%9}, {%0,%1,%2,%3};"
        : "+f"(d[0]), "+f"(d[1]), "+f"(d[2]), "+f"(d[3])
        : "r"(a[0]), "r"(a[1]), "r"(a[2]), "r"(a[3]), "r"(b[0]), "r"(b[1]));
}

// ---------------- HMMA fp16 GEMM: C[N,M] = A[N,K] @ B[M,K]^T + epilogue -----
// CTA 128x128, BK=128 (ROWB=272 -> (17r+c)&7 bijective, conflict-free
// ldmatrix). 3-stage cp.async pipeline with mbarriers (free-running, no
// per-chunk __syncthreads). 8 warps (4x2), warp tile 32x64 — per-warp MMA
// sequence identical to the R8 winner; only the chunk length doubled
// (half the chunk boundaries). 208KB SMEM -> 1 CTA/SM.
#define BM 128
#define BN 128
#define BK 128
#define ROWB 272
#define TILEB (128 * ROWB)           // 34816 per tile (A or B)
#define STAGEB (2 * TILEB)           // 69632 per stage
#define GSMEM (64 + 3 * STAGEB)      // 208960

template<bool RELU, bool HASRES, bool RESHALF, bool OUTHALF>
__global__ void __launch_bounds__(256) gemm16_kernel(
    const __half* __restrict__ A, const __half* __restrict__ B,
    const float* __restrict__ bias, const void* __restrict__ resv,
    void* __restrict__ Cv, int K, int M)
{
    extern __shared__ __align__(16) char smem[];
    const uint32_t sb = smem_u32(smem);
    const uint32_t tb = sb + 64;
    const int tid = threadIdx.x;
    const int lane = tid & 31;
    const int wid = tid >> 5;
    const int wm = wid & 3;
    const int wn = wid >> 2;
    const int bm = blockIdx.y * BM;
    const int bn = blockIdx.x * BN;

    if (tid == 0) {
#pragma unroll
        for (int s = 0; s < 3; s++) {
            mbar_init(sb + s * 8, 256);        // full[s]
            mbar_init(sb + 24 + s * 8, 256);   // free[s]
        }
    }
    __syncthreads();

    // cp.async: tile = 128 rows x 16 segs(16B) = 2048 segs, 8/thread/tile
    uint32_t soff[8];
    const __half* agp[8];
    const __half* bgp[8];
#pragma unroll
    for (int i = 0; i < 8; i++) {
        int seg = tid + i * 256;
        int r = seg >> 4, c = seg & 15;
        soff[i] = r * ROWB + c * 16;
        agp[i] = A + (size_t)(bm + r) * K + c * 8;
        bgp[i] = B + (size_t)(bn + r) * K + c * 8;
    }

    uint32_t a_off[2], b_off[4];
#pragma unroll
    for (int mf = 0; mf < 2; mf++)
        a_off[mf] = (wm * 32 + mf * 16 + (lane & 15)) * ROWB + ((lane >> 4) * 16);
#pragma unroll
    for (int p = 0; p < 4; p++)
        b_off[p] = (wn * 64 + p * 16 + ((lane >> 4) << 3) + (lane & 7)) * ROWB
                 + (((lane >> 3) & 1) * 16);

    float acc[2][8][4];
#pragma unroll
    for (int i = 0; i < 2; i++)
#pragma unroll
        for (int j = 0; j < 8; j++)
#pragma unroll
            for (int t = 0; t < 4; t++) acc[i][j][t] = 0.f;

    const int NC = K >> 7;   // 4 (K=512) or 16 (K=2048)

    // prologue: prefetch chunks 0 and 1 (stages 0, 1)
#pragma unroll
    for (int pc = 0; pc < 2; pc++) {
        const uint32_t base = tb + pc * STAGEB;
        const int ko = pc * BK;
#pragma unroll
        for (int i = 0; i < 8; i++) {
            cp_async16(base + soff[i], agp[i] + ko);
            cp_async16(base + TILEB + soff[i], bgp[i] + ko);
        }
        cpasync_mbar_arrive(sb + pc * 8);
    }

    int st = 0;            // compute stage
    uint32_t pful = 0;     // full-wait parity
    int pt = 2;            // prefetch stage
    uint32_t wfree = 1;    // free-wait parity

#pragma unroll 1
    for (int chunk = 0; chunk < NC; chunk++) {
        const int pc = chunk + 2;
        if (pc < NC) {
            if (pc >= 3) mbar_wait(sb + 24 + pt * 8, wfree);
            const uint32_t base = tb + pt * STAGEB;
            const int ko = pc * BK;
#pragma unroll
            for (int i = 0; i < 8; i++) {
                cp_async16(base + soff[i], agp[i] + ko);
                cp_async16(base + TILEB + soff[i], bgp[i] + ko);
            }
            cpasync_mbar_arrive(sb + pt * 8);
            if (pt == 2) { pt = 0; wfree ^= 1u; } else pt++;
        }

        mbar_wait(sb + st * 8, pful);
        const uint32_t ab = tb + st * STAGEB;
        const uint32_t bb = ab + TILEB;
#pragma unroll
        for (int ks = 0; ks < 8; ks++) {
            uint32_t afr[2][4], bfr[4][4];
            ldm_x4(afr[0], ab + a_off[0] + ks * 32);
            ldm_x4(afr[1], ab + a_off[1] + ks * 32);
#pragma unroll
            for (int p = 0; p < 4; p++) ldm_x4(bfr[p], bb + b_off[p] + ks * 32);
#pragma unroll
            for (int mf = 0; mf < 2; mf++)
#pragma unroll
                for (int nf = 0; nf < 8; nf++)
                    mma16816(acc[mf][nf], afr[mf], &bfr[nf >> 1][(nf & 1) * 2]);
        }
        mbar_arrive(sb + 24 + st * 8);
        if (st == 2) { st = 0; pful ^= 1u; } else st++;
    }

    // epilogue
    const int mrow = bm + wm * 32 + (lane >> 2);
    const int ncol = bn + wn * 64 + (lane & 3) * 2;
#pragma unroll
    for (int mf = 0; mf < 2; mf++) {
#pragma unroll
        for (int half8 = 0; half8 < 2; half8++) {
            const int row = mrow + mf * 16 + half8 * 8;
#pragma unroll
            for (int nf = 0; nf < 8; nf++) {
                const int col = ncol + nf * 8;
                float c0 = acc[mf][nf][half8 * 2 + 0];
                float c1 = acc[mf][nf][half8 * 2 + 1];
                float2 b2 = *(const float2*)&bias[col];
                c0 += b2.x; c1 += b2.y;
                if (RELU) { c0 = fmaxf(c0, 0.f); c1 = fmaxf(c1, 0.f); }
                if (HASRES) {
                    if (RESHALF) {
                        __half2 r2 = *(const __half2*)((const __half*)resv + (size_t)row * M + col);
                        float2 rf = __half22float2(r2);
                        c0 += rf.x; c1 += rf.y;
                    } else {
                        float2 r2 = *(const float2*)((const float*)resv + (size_t)row * M + col);
                        c0 += r2.x; c1 += r2.y;
                    }
                }
                if (OUTHALF) {
                    *(__half2*)((__half*)Cv + (size_t)row * M + col) =
                        __floats2half2_rn(c0, c1);
                } else {
                    *(float2*)((float*)Cv + (size_t)row * M + col) =
                        make_float2(c0, c1);
                }
            }
        }
    }
}

// ---------------- LayerNorm (fp32 in) -> fp16, warp-per-row -------------------
__global__ void __launch_bounds__(256) ln_kernel(
    const float* __restrict__ x, const float* __restrict__ gamma,
    const float* __restrict__ beta, __half* __restrict__ y)
{
    const int w = threadIdx.x >> 5, lane = threadIdx.x & 31;
    const size_t row = (size_t)blockIdx.x * 8 + w;
    const float4* xp = (const float4*)(x + row * EMBED);
    float4 v[4];
    float s = 0.f, s2 = 0.f;
#pragma unroll
    for (int k = 0; k < 4; k++) {
        v[k] = xp[k * 32 + lane];
        s  += v[k].x + v[k].y + v[k].z + v[k].w;
        s2 += v[k].x*v[k].x + v[k].y*v[k].y + v[k].z*v[k].z + v[k].w*v[k].w;
    }
#pragma unroll
    for (int o = 16; o > 0; o >>= 1) {
        s  += __shfl_xor_sync(0xffffffffu, s,  o);
        s2 += __shfl_xor_sync(0xffffffffu, s2, o);
    }
    const float mu = s * (1.0f / EMBED);
    const float inv = rsqrtf(s2 * (1.0f / EMBED) - mu * mu + 1e-5f);
    __half2* yp = (__half2*)(y + row * EMBED);
#pragma unroll
    for (int k = 0; k < 4; k++) {
        float4 g4 = ((const float4*)gamma)[k * 32 + lane];
        float4 b4 = ((const float4*)beta)[k * 32 + lane];
        yp[(k * 32 + lane) * 2] =
            __floats2half2_rn((v[k].x - mu) * inv * g4.x + b4.x,
                              (v[k].y - mu) * inv * g4.y + b4.y);
        yp[(k * 32 + lane) * 2 + 1] =
            __floats2half2_rn((v[k].z - mu) * inv * g4.z + b4.z,
                              (v[k].w - mu) * inv * g4.w + b4.w);
    }
}

// ---------------- LayerNorm (fp16 in) -> fp16, warp-per-row -------------------
__global__ void __launch_bounds__(256) ln_h_kernel(
    const __half* __restrict__ x, const float* __restrict__ gamma,
    const float* __restrict__ beta, __half* __restrict__ y)
{
    const int w = threadIdx.x >> 5, lane = threadIdx.x & 31;
    const size_t row = (size_t)blockIdx.x * 8 + w;
    const uint4* xp = (const uint4*)(x + row * EMBED);
    uint4 raw[2];
    float f[16];
    float s = 0.f, s2 = 0.f;
#pragma unroll
    for (int k = 0; k < 2; k++) {
        raw[k] = xp[k * 32 + lane];
        const __half2* hp = (const __half2*)&raw[k];
#pragma unroll
        for (int j = 0; j < 4; j++) {
            float2 fj = __half22float2(hp[j]);
            f[k * 8 + j * 2]     = fj.x;
            f[k * 8 + j * 2 + 1] = fj.y;
            s  += fj.x + fj.y;
            s2 += fj.x * fj.x + fj.y * fj.y;
        }
    }
#pragma unroll
    for (int o = 16; o > 0; o >>= 1) {
        s  += __shfl_xor_sync(0xffffffffu, s,  o);
        s2 += __shfl_xor_sync(0xffffffffu, s2, o);
    }
    const float mu = s * (1.0f / EMBED);
    const float inv = rsqrtf(s2 * (1.0f / EMBED) - mu * mu + 1e-5f);
    __half2* yp = (__half2*)(y + row * EMBED);
#pragma unroll
    for (int k = 0; k < 2; k++) {
        const int base4 = (k * 32 + lane) * 2;
#pragma unroll
        for (int q = 0; q < 2; q++) {
            float4 g4 = ((const float4*)gamma)[base4 + q];
            float4 b4 = ((const float4*)beta)[base4 + q];
            yp[(base4 + q) * 2] =
                __floats2half2_rn((f[k*8 + q*4 + 0] - mu) * inv * g4.x + b4.x,
                                  (f[k*8 + q*4 + 1] - mu) * inv * g4.y + b4.y);
            yp[(base4 + q) * 2 + 1] =
                __floats2half2_rn((f[k*8 + q*4 + 2] - mu) * inv * g4.z + b4.z,
                                  (f[k*8 + q*4 + 3] - mu) * inv * g4.w + b4.w);
        }
    }
}

// ---------------- per-node attention, warp-per-node ---------------------------
__global__ void __launch_bounds__(256) attn_kernel(
    const __half* __restrict__ qkv, __half* __restrict__ out)
{
    const int w = threadIdx.x >> 5, lane = threadIdx.x & 31;
    const size_t node = (size_t)blockIdx.x * 8 + w;

    __shared__ __half s[8][QKVDIM];
    __shared__ float sa[8][64];

    const uint4* rp = (const uint4*)(qkv + node * QKVDIM);
    uint4* sp = (uint4*)s[w];
#pragma unroll
    for (int i = 0; i < 6; i++) sp[i * 32 + lane] = rp[i * 32 + lane];
    __syncwarp();

    const __half* sq = s[w];
    const __half* sk = s[w] + EMBED;
    const __half* sv = s[w] + 2 * EMBED;

    float sc[2];
#pragma unroll
    for (int pi = 0; pi < 2; pi++) {
        const int p = lane + pi * 32;
        const int h = p >> 3, g = p & 7;
        const __half2* qh = (const __half2*)(sq + h * HDIM);
        const __half2* kh = (const __half2*)(sk + g * HDIM);
        float a = 0.f;
#pragma unroll
        for (int dd = 0; dd < 32; dd++) {
            const int d = (dd + g * 4 + (h & 3) * 8) & 31;
            float2 a2 = __half22float2(qh[d]);
            float2 b2 = __half22float2(kh[d]);
            a += a2.x * b2.x + a2.y * b2.y;
        }
        sc[pi] = a * 0.125f;
    }

#pragma unroll
    for (int pi = 0; pi < 2; pi++) {
        float m = sc[pi];
#pragma unroll
        for (int o = 4; o > 0; o >>= 1)
            m = fmaxf(m, __shfl_xor_sync(0xffffffffu, m, o));
        float e = expf(sc[pi] - m);
        float ssum = e;
#pragma unroll
        for (int o = 4; o > 0; o >>= 1)
            ssum += __shfl_xor_sync(0xffffffffu, ssum, o);
        sa[w][lane + pi * 32] = e / ssum;
    }
    __syncwarp();

    __half* op = out + node * EMBED;
#pragma unroll
    for (int h = 0; h < NHEADS; h++) {
        float o0 = 0.f, o1 = 0.f;
#pragma unroll
        for (int g = 0; g < 8; g++) {
            const float a = sa[w][h * 8 + g];
            o0 += a * __half2float(sv[g * HDIM + lane]);
            o1 += a * __half2float(sv[g * HDIM + 32 + lane]);
        }
        op[h * HDIM + lane]      = __float2half(o0);
        op[h * HDIM + 32 + lane] = __float2half(o1);
    }
}

// ---------------- weight conversion -------------------------------------------
__global__ void __launch_bounds__(256) f2h_all_kernel(
    const float* __restrict__ Wq, const float* __restrict__ Wk,
    const float* __restrict__ Wv, const float* __restrict__ Wo,
    const float* __restrict__ W1, const float* __restrict__ W2,
    __half* __restrict__ wqkv, __half* __restrict__ wo,
    __half* __restrict__ w1, __half* __restrict__ w2)
{
    int y = blockIdx.y;
    const float* s; __half* d; int n4;
    if      (y == 0) { s = Wq; d = wqkv;                 n4 = EMBED*EMBED/4; }
    else if (y == 1) { s = Wk; d = wqkv + EMBED*EMBED;   n4 = EMBED*EMBED/4; }
    else if (y == 2) { s = Wv; d = wqkv + 2*EMBED*EMBED; n4 = EMBED*EMBED/4; }
    else if (y == 3) { s = Wo; d = wo;                   n4 = EMBED*EMBED/4; }
    else if (y == 4) { s = W1; d = w1;                   n4 = FFDIM*EMBED/4; }
    else             { s = W2; d = w2;                   n4 = FFDIM*EMBED/4; }
    for (int i = blockIdx.x * blockDim.x + threadIdx.x; i < n4; i += gridDim.x * blockDim.x) {
        float4 v = ((const float4*)s)[i];
        __half2* dp = (__half2*)d + i * 2;
        dp[0] = __floats2half2_rn(v.x, v.y);
        dp[1] = __floats2half2_rn(v.z, v.w);
    }
}

__global__ void __launch_bounds__(256) bias_cat_kernel(
    const float* __restrict__ bq, const float* __restrict__ bk,
    const float* __restrict__ bv, float* __restrict__ bqkv)
{
    int i = blockIdx.x * 256 + threadIdx.x;
    float val = (i < EMBED) ? bq[i] : (i < 2 * EMBED) ? bk[i - EMBED] : bv[i - 2 * EMBED];
    bqkv[i] = val;
}

// ---------------- host orchestration -----------------------------------------
extern "C" void kernel_launch(void* const* d_in, const int* in_sizes, int n_in,
                              void* d_out, int out_size)
{
    const float* x   = (const float*)d_in[0];
    const float* Wq  = (const float*)d_in[1];
    const float* bq  = (const float*)d_in[2];
    const float* Wk  = (const float*)d_in[3];
    const float* bk  = (const float*)d_in[4];
    const float* Wv  = (const float*)d_in[5];
    const float* bv  = (const float*)d_in[6];
    const float* Wo  = (const float*)d_in[7];
    const float* bo  = (const float*)d_in[8];
    const float* W1  = (const float*)d_in[9];
    const float* b1  = (const float*)d_in[10];
    const float* W2  = (const float*)d_in[11];
    const float* b2  = (const float*)d_in[12];
    const float* g1  = (const float*)d_in[13];
    const float* be1 = (const float*)d_in[14];
    const float* g2  = (const float*)d_in[15];
    const float* be2 = (const float*)d_in[16];
    float* out = (float*)d_out;

    __half *h, *qkv, *attnh, *ffh, *wqkv, *wo, *w1, *w2, *x1h;
    float *bqkv;
    cudaGetSymbolAddress((void**)&h,     g_h);
    cudaGetSymbolAddress((void**)&qkv,   g_qkv);
    cudaGetSymbolAddress((void**)&attnh, g_attnh);
    cudaGetSymbolAddress((void**)&x1h,   g_x1h);
    cudaGetSymbolAddress((void**)&ffh,   g_ffh);
    cudaGetSymbolAddress((void**)&wqkv,  g_wqkv);
    cudaGetSymbolAddress((void**)&wo,    g_wo);
    cudaGetSymbolAddress((void**)&w1,    g_w1);
    cudaGetSymbolAddress((void**)&w2,    g_w2);
    cudaGetSymbolAddress((void**)&bqkv,  g_bqkv);

    cudaFuncSetAttribute(gemm16_kernel<false,false,false,true>,
                         cudaFuncAttributeMaxDynamicSharedMemorySize, GSMEM);
    cudaFuncSetAttribute(gemm16_kernel<false,true,false,true>,
                         cudaFuncAttributeMaxDynamicSharedMemorySize, GSMEM);
    cudaFuncSetAttribute(gemm16_kernel<true,false,false,true>,
                         cudaFuncAttributeMaxDynamicSharedMemorySize, GSMEM);
    cudaFuncSetAttribute(gemm16_kernel<false,true,true,false>,
                         cudaFuncAttributeMaxDynamicSharedMemorySize, GSMEM);

    {
        dim3 g(256, 6);
        f2h_all_kernel<<<g, 256>>>(Wq, Wk, Wv, Wo, W1, W2, wqkv, wo, w1, w2);
        bias_cat_kernel<<<QKVDIM / 256, 256>>>(bq, bk, bv, bqkv);
    }

    // 1) h = LN1(x) -> fp16
    ln_kernel<<<N_NODES / 8, 256>>>(x, g1, be1, h);

    // 2) qkv = h @ Wqkv^T + bqkv (fp16 out)
    dim3 grdQKV(QKVDIM / BN, N_NODES / BM);   // (12, 512)
    gemm16_kernel<false,false,false,true><<<grdQKV, 256, GSMEM>>>(h, wqkv, bqkv, nullptr, qkv, EMBED, QKVDIM);

    // 3) per-node attention -> fp16
    attn_kernel<<<N_NODES / 8, 256>>>(qkv, attnh);

    // 4) x1h = x + attnh @ Wo^T + bo (fp16 out, fp32 residual in)
    dim3 grdE(EMBED / BN, N_NODES / BM);      // (4, 512)
    gemm16_kernel<false,true,false,true><<<grdE, 256, GSMEM>>>(attnh, wo, bo, x, x1h, EMBED, EMBED);

    // 5) h = LN2(x1h) -> fp16
    ln_h_kernel<<<N_NODES / 8, 256>>>(x1h, g2, be2, h);

    // 6) ffh = relu(h @ W1^T + b1) -> fp16
    dim3 grdF(FFDIM / BN, N_NODES / BM);      // (16, 512)
    gemm16_kernel<true,false,false,true><<<grdF, 256, GSMEM>>>(h, w1, b1, nullptr, ffh, EMBED, FFDIM);

    // 7) out = x1h + ffh @ W2^T + b2 (fp32 out, fp16 residual in)
    gemm16_kernel<false,true,true,false><<<grdE, 256, GSMEM>>>(ffh, w2, b2, x1h, out, FFDIM, EMBED);
}

// round 13
// speedup vs baseline: 1.1330x; 1.1330x over previous
#include <cuda_runtime.h>
#include <cuda_fp16.h>
#include <math.h>
#include <stdint.h>

#define N_NODES 65536
#define EMBED 512
#define FFDIM 2048
#define QKVDIM 1536
#define NHEADS 8
#define HDIM 64

// ---------------- scratch ----------------------------------------------------
__device__ __half g_h[(size_t)N_NODES * EMBED];
__device__ __half g_qkv[(size_t)N_NODES * QKVDIM];
__device__ __half g_attnh[(size_t)N_NODES * EMBED];
__device__ __half g_x1h[(size_t)N_NODES * EMBED];
__device__ __half g_ffh[(size_t)N_NODES * FFDIM];
__device__ __half g_wqkv[QKVDIM * EMBED];
__device__ float  g_bqkv[QKVDIM];
__device__ __half g_wo[EMBED * EMBED];
__device__ __half g_w1[FFDIM * EMBED];
__device__ __half g_w2[EMBED * FFDIM];

// ---------------- ptx helpers ------------------------------------------------
__device__ __forceinline__ uint32_t smem_u32(const void* p) {
    uint32_t a;
    asm("{ .reg .u64 t; cvta.to.shared.u64 t, %1; cvt.u32.u64 %0, t; }" : "=r"(a) : "l"(p));
    return a;
}
__device__ __forceinline__ void cp_async16(uint32_t saddr, const void* gaddr) {
    asm volatile("cp.async.cg.shared.global [%0], [%1], 16;\n" :: "r"(saddr), "l"(gaddr));
}
__device__ __forceinline__ void cpasync_mbar_arrive(uint32_t mbar) {
    asm volatile("cp.async.mbarrier.arrive.noinc.shared.b64 [%0];" :: "r"(mbar) : "memory");
}
__device__ __forceinline__ void mbar_init(uint32_t mbar, uint32_t cnt) {
    asm volatile("mbarrier.init.shared.b64 [%0], %1;" :: "r"(mbar), "r"(cnt) : "memory");
}
__device__ __forceinline__ void mbar_arrive(uint32_t mbar) {
    asm volatile("mbarrier.arrive.shared.b64 _, [%0];" :: "r"(mbar) : "memory");
}
__device__ __forceinline__ void mbar_wait(uint32_t mbar, uint32_t parity) {
    asm volatile(
        "{\n\t.reg .pred P;\n\t"
        "WL%=:\n\t"
        "mbarrier.try_wait.parity.acquire.cta.shared::cta.b64 P, [%0], %1, 0x989680;\n\t"
        "@P bra WD%=;\n\t"
        "bra WL%=;\n\t"
        "WD%=:\n\t}"
        :: "r"(mbar), "r"(parity) : "memory");
}
__device__ __forceinline__ void ldm_x4(uint32_t* r, uint32_t addr) {
    asm volatile("ldmatrix.sync.aligned.m8n8.x4.shared.b16 {%0,%1,%2,%3}, [%4];"
                 : "=r"(r[0]), "=r"(r[1]), "=r"(r[2]), "=r"(r[3]) : "r"(addr));
}
__device__ __forceinline__ void mma16816(float* d, const uint32_t* a, const uint32_t* b) {
    asm volatile(
        "mma.sync.aligned.m16n8k16.row.col.f32.f16.f16.f32 "
        "{%0,%1,%2,%3}, {%4,%5,%6,%7}, {%8,%9}, {%0,%1,%2,%3};"
        : "+f"(d[0]), "+f"(d[1]), "+f"(d[2]), "+f"(d[3])
        : "r"(a[0]), "r"(a[1]), "r"(a[2]), "r"(a[3]), "r"(b[0]), "r"(b[1]));
}

// ---------------- HMMA fp16 GEMM: C[N,M] = A[N,K] @ B[M,K]^T + epilogue -----
// CTA 128x128, BK=64, ROWB=144 (conflict-free ldmatrix). 512 threads =
// 16 warps (4 M-groups x 4 N-groups), warp tile 32x32. 3-stage cp.async
// pipeline with mbarriers (free-running). __launch_bounds__(512,2) forces
// 2 CTAs/SM = 32 warps/SM (2x the R8/R11 occupancy) — the one untested
// direction of the occupancy axis. Per-element K-accumulation order is
// unchanged -> identical numerics to R11.
#define BM 128
#define BN 128
#define BK 64
#define ROWB 144
#define TILEB (128 * ROWB)           // 18432 per tile (A or B)
#define STAGEB (2 * TILEB)           // 36864 per stage
#define GSMEM (64 + 3 * STAGEB)      // 110656
#define GTHREADS 512

template<bool RELU, bool HASRES, bool RESHALF, bool OUTHALF>
__global__ void __launch_bounds__(GTHREADS, 2) gemm16_kernel(
    const __half* __restrict__ A, const __half* __restrict__ B,
    const float* __restrict__ bias, const void* __restrict__ resv,
    void* __restrict__ Cv, int K, int M)
{
    extern __shared__ __align__(16) char smem[];
    const uint32_t sb = smem_u32(smem);
    const uint32_t tb = sb + 64;
    const int tid = threadIdx.x;
    const int lane = tid & 31;
    const int wid = tid >> 5;
    const int wm = wid & 3;          // 0..3, 32 rows
    const int wn = wid >> 2;         // 0..3, 32 cols
    const int bm = blockIdx.y * BM;
    const int bn = blockIdx.x * BN;

    if (tid == 0) {
#pragma unroll
        for (int s = 0; s < 3; s++) {
            mbar_init(sb + s * 8, GTHREADS);        // full[s]
            mbar_init(sb + 24 + s * 8, GTHREADS);   // free[s]
        }
    }
    __syncthreads();

    // cp.async slots: tile = 1024 segs(16B), 2/thread/tile
    uint32_t soff[2];
    const __half* agp[2];
    const __half* bgp[2];
#pragma unroll
    for (int i = 0; i < 2; i++) {
        int seg = tid + i * GTHREADS;
        int r = seg >> 3, c = seg & 7;
        soff[i] = r * ROWB + c * 16;
        agp[i] = A + (size_t)(bm + r) * K + c * 8;
        bgp[i] = B + (size_t)(bn + r) * K + c * 8;
    }

    uint32_t a_off[2], b_off[2];
#pragma unroll
    for (int mf = 0; mf < 2; mf++)
        a_off[mf] = (wm * 32 + mf * 16 + (lane & 15)) * ROWB + ((lane >> 4) * 16);
#pragma unroll
    for (int p = 0; p < 2; p++)
        b_off[p] = (wn * 32 + p * 16 + ((lane >> 4) << 3) + (lane & 7)) * ROWB
                 + (((lane >> 3) & 1) * 16);

    float acc[2][4][4];
#pragma unroll
    for (int i = 0; i < 2; i++)
#pragma unroll
        for (int j = 0; j < 4; j++)
#pragma unroll
            for (int t = 0; t < 4; t++) acc[i][j][t] = 0.f;

    const int NC = K >> 6;

    // prologue: prefetch chunks 0 and 1 (stages 0, 1)
#pragma unroll
    for (int pc = 0; pc < 2; pc++) {
        const uint32_t base = tb + pc * STAGEB;
        const int ko = pc * BK;
#pragma unroll
        for (int i = 0; i < 2; i++) {
            cp_async16(base + soff[i], agp[i] + ko);
            cp_async16(base + TILEB + soff[i], bgp[i] + ko);
        }
        cpasync_mbar_arrive(sb + pc * 8);
    }

    int st = 0;
    uint32_t pful = 0;
    int pt = 2;
    uint32_t wfree = 1;

#pragma unroll 1
    for (int chunk = 0; chunk < NC; chunk++) {
        const int pc = chunk + 2;
        if (pc < NC) {
            if (pc >= 3) mbar_wait(sb + 24 + pt * 8, wfree);
            const uint32_t base = tb + pt * STAGEB;
            const int ko = pc * BK;
#pragma unroll
            for (int i = 0; i < 2; i++) {
                cp_async16(base + soff[i], agp[i] + ko);
                cp_async16(base + TILEB + soff[i], bgp[i] + ko);
            }
            cpasync_mbar_arrive(sb + pt * 8);
            if (pt == 2) { pt = 0; wfree ^= 1u; } else pt++;
        }

        mbar_wait(sb + st * 8, pful);
        const uint32_t ab = tb + st * STAGEB;
        const uint32_t bb = ab + TILEB;
#pragma unroll
        for (int ks = 0; ks < 4; ks++) {
            uint32_t afr[2][4], bfr[2][4];
            ldm_x4(afr[0], ab + a_off[0] + ks * 32);
            ldm_x4(afr[1], ab + a_off[1] + ks * 32);
            ldm_x4(bfr[0], bb + b_off[0] + ks * 32);
            ldm_x4(bfr[1], bb + b_off[1] + ks * 32);
#pragma unroll
            for (int mf = 0; mf < 2; mf++)
#pragma unroll
                for (int nf = 0; nf < 4; nf++)
                    mma16816(acc[mf][nf], afr[mf], &bfr[nf >> 1][(nf & 1) * 2]);
        }
        mbar_arrive(sb + 24 + st * 8);
        if (st == 2) { st = 0; pful ^= 1u; } else st++;
    }

    // epilogue: warp tile 32x32 at (wm*32, wn*32)
    const int mrow = bm + wm * 32 + (lane >> 2);
    const int ncol = bn + wn * 32 + (lane & 3) * 2;
#pragma unroll
    for (int mf = 0; mf < 2; mf++) {
#pragma unroll
        for (int half8 = 0; half8 < 2; half8++) {
            const int row = mrow + mf * 16 + half8 * 8;
#pragma unroll
            for (int nf = 0; nf < 4; nf++) {
                const int col = ncol + nf * 8;
                float c0 = acc[mf][nf][half8 * 2 + 0];
                float c1 = acc[mf][nf][half8 * 2 + 1];
                float2 b2 = *(const float2*)&bias[col];
                c0 += b2.x; c1 += b2.y;
                if (RELU) { c0 = fmaxf(c0, 0.f); c1 = fmaxf(c1, 0.f); }
                if (HASRES) {
                    if (RESHALF) {
                        __half2 r2 = *(const __half2*)((const __half*)resv + (size_t)row * M + col);
                        float2 rf = __half22float2(r2);
                        c0 += rf.x; c1 += rf.y;
                    } else {
                        float2 r2 = *(const float2*)((const float*)resv + (size_t)row * M + col);
                        c0 += r2.x; c1 += r2.y;
                    }
                }
                if (OUTHALF) {
                    *(__half2*)((__half*)Cv + (size_t)row * M + col) =
                        __floats2half2_rn(c0, c1);
                } else {
                    *(float2*)((float*)Cv + (size_t)row * M + col) =
                        make_float2(c0, c1);
                }
            }
        }
    }
}

// ---------------- LayerNorm (fp32 in) -> fp16, warp-per-row -------------------
__global__ void __launch_bounds__(256) ln_kernel(
    const float* __restrict__ x, const float* __restrict__ gamma,
    const float* __restrict__ beta, __half* __restrict__ y)
{
    const int w = threadIdx.x >> 5, lane = threadIdx.x & 31;
    const size_t row = (size_t)blockIdx.x * 8 + w;
    const float4* xp = (const float4*)(x + row * EMBED);
    float4 v[4];
    float s = 0.f, s2 = 0.f;
#pragma unroll
    for (int k = 0; k < 4; k++) {
        v[k] = xp[k * 32 + lane];
        s  += v[k].x + v[k].y + v[k].z + v[k].w;
        s2 += v[k].x*v[k].x + v[k].y*v[k].y + v[k].z*v[k].z + v[k].w*v[k].w;
    }
#pragma unroll
    for (int o = 16; o > 0; o >>= 1) {
        s  += __shfl_xor_sync(0xffffffffu, s,  o);
        s2 += __shfl_xor_sync(0xffffffffu, s2, o);
    }
    const float mu = s * (1.0f / EMBED);
    const float inv = rsqrtf(s2 * (1.0f / EMBED) - mu * mu + 1e-5f);
    __half2* yp = (__half2*)(y + row * EMBED);
#pragma unroll
    for (int k = 0; k < 4; k++) {
        float4 g4 = ((const float4*)gamma)[k * 32 + lane];
        float4 b4 = ((const float4*)beta)[k * 32 + lane];
        yp[(k * 32 + lane) * 2] =
            __floats2half2_rn((v[k].x - mu) * inv * g4.x + b4.x,
                              (v[k].y - mu) * inv * g4.y + b4.y);
        yp[(k * 32 + lane) * 2 + 1] =
            __floats2half2_rn((v[k].z - mu) * inv * g4.z + b4.z,
                              (v[k].w - mu) * inv * g4.w + b4.w);
    }
}

// ---------------- LayerNorm (fp16 in) -> fp16, warp-per-row -------------------
__global__ void __launch_bounds__(256) ln_h_kernel(
    const __half* __restrict__ x, const float* __restrict__ gamma,
    const float* __restrict__ beta, __half* __restrict__ y)
{
    const int w = threadIdx.x >> 5, lane = threadIdx.x & 31;
    const size_t row = (size_t)blockIdx.x * 8 + w;
    const uint4* xp = (const uint4*)(x + row * EMBED);
    uint4 raw[2];
    float f[16];
    float s = 0.f, s2 = 0.f;
#pragma unroll
    for (int k = 0; k < 2; k++) {
        raw[k] = xp[k * 32 + lane];
        const __half2* hp = (const __half2*)&raw[k];
#pragma unroll
        for (int j = 0; j < 4; j++) {
            float2 fj = __half22float2(hp[j]);
            f[k * 8 + j * 2]     = fj.x;
            f[k * 8 + j * 2 + 1] = fj.y;
            s  += fj.x + fj.y;
            s2 += fj.x * fj.x + fj.y * fj.y;
        }
    }
#pragma unroll
    for (int o = 16; o > 0; o >>= 1) {
        s  += __shfl_xor_sync(0xffffffffu, s,  o);
        s2 += __shfl_xor_sync(0xffffffffu, s2, o);
    }
    const float mu = s * (1.0f / EMBED);
    const float inv = rsqrtf(s2 * (1.0f / EMBED) - mu * mu + 1e-5f);
    __half2* yp = (__half2*)(y + row * EMBED);
#pragma unroll
    for (int k = 0; k < 2; k++) {
        const int base4 = (k * 32 + lane) * 2;
#pragma unroll
        for (int q = 0; q < 2; q++) {
            float4 g4 = ((const float4*)gamma)[base4 + q];
            float4 b4 = ((const float4*)beta)[base4 + q];
            yp[(base4 + q) * 2] =
                __floats2half2_rn((f[k*8 + q*4 + 0] - mu) * inv * g4.x + b4.x,
                                  (f[k*8 + q*4 + 1] - mu) * inv * g4.y + b4.y);
            yp[(base4 + q) * 2 + 1] =
                __floats2half2_rn((f[k*8 + q*4 + 2] - mu) * inv * g4.z + b4.z,
                                  (f[k*8 + q*4 + 3] - mu) * inv * g4.w + b4.w);
        }
    }
}

// ---------------- per-node attention, warp-per-node ---------------------------
__global__ void __launch_bounds__(256) attn_kernel(
    const __half* __restrict__ qkv, __half* __restrict__ out)
{
    const int w = threadIdx.x >> 5, lane = threadIdx.x & 31;
    const size_t node = (size_t)blockIdx.x * 8 + w;

    __shared__ __half s[8][QKVDIM];
    __shared__ float sa[8][64];

    const uint4* rp = (const uint4*)(qkv + node * QKVDIM);
    uint4* sp = (uint4*)s[w];
#pragma unroll
    for (int i = 0; i < 6; i++) sp[i * 32 + lane] = rp[i * 32 + lane];
    __syncwarp();

    const __half* sq = s[w];
    const __half* sk = s[w] + EMBED;
    const __half* sv = s[w] + 2 * EMBED;

    float sc[2];
#pragma unroll
    for (int pi = 0; pi < 2; pi++) {
        const int p = lane + pi * 32;
        const int h = p >> 3, g = p & 7;
        const __half2* qh = (const __half2*)(sq + h * HDIM);
        const __half2* kh = (const __half2*)(sk + g * HDIM);
        float a = 0.f;
#pragma unroll
        for (int dd = 0; dd < 32; dd++) {
            const int d = (dd + g * 4 + (h & 3) * 8) & 31;
            float2 a2 = __half22float2(qh[d]);
            float2 b2 = __half22float2(kh[d]);
            a += a2.x * b2.x + a2.y * b2.y;
        }
        sc[pi] = a * 0.125f;
    }

#pragma unroll
    for (int pi = 0; pi < 2; pi++) {
        float m = sc[pi];
#pragma unroll
        for (int o = 4; o > 0; o >>= 1)
            m = fmaxf(m, __shfl_xor_sync(0xffffffffu, m, o));
        float e = expf(sc[pi] - m);
        float ssum = e;
#pragma unroll
        for (int o = 4; o > 0; o >>= 1)
            ssum += __shfl_xor_sync(0xffffffffu, ssum, o);
        sa[w][lane + pi * 32] = e / ssum;
    }
    __syncwarp();

    __half* op = out + node * EMBED;
#pragma unroll
    for (int h = 0; h < NHEADS; h++) {
        float o0 = 0.f, o1 = 0.f;
#pragma unroll
        for (int g = 0; g < 8; g++) {
            const float a = sa[w][h * 8 + g];
            o0 += a * __half2float(sv[g * HDIM + lane]);
            o1 += a * __half2float(sv[g * HDIM + 32 + lane]);
        }
        op[h * HDIM + lane]      = __float2half(o0);
        op[h * HDIM + 32 + lane] = __float2half(o1);
    }
}

// ---------------- weight conversion -------------------------------------------
__global__ void __launch_bounds__(256) f2h_all_kernel(
    const float* __restrict__ Wq, const float* __restrict__ Wk,
    const float* __restrict__ Wv, const float* __restrict__ Wo,
    const float* __restrict__ W1, const float* __restrict__ W2,
    __half* __restrict__ wqkv, __half* __restrict__ wo,
    __half* __restrict__ w1, __half* __restrict__ w2)
{
    int y = blockIdx.y;
    const float* s; __half* d; int n4;
    if      (y == 0) { s = Wq; d = wqkv;                 n4 = EMBED*EMBED/4; }
    else if (y == 1) { s = Wk; d = wqkv + EMBED*EMBED;   n4 = EMBED*EMBED/4; }
    else if (y == 2) { s = Wv; d = wqkv + 2*EMBED*EMBED; n4 = EMBED*EMBED/4; }
    else if (y == 3) { s = Wo; d = wo;                   n4 = EMBED*EMBED/4; }
    else if (y == 4) { s = W1; d = w1;                   n4 = FFDIM*EMBED/4; }
    else             { s = W2; d = w2;                   n4 = FFDIM*EMBED/4; }
    for (int i = blockIdx.x * blockDim.x + threadIdx.x; i < n4; i += gridDim.x * blockDim.x) {
        float4 v = ((const float4*)s)[i];
        __half2* dp = (__half2*)d + i * 2;
        dp[0] = __floats2half2_rn(v.x, v.y);
        dp[1] = __floats2half2_rn(v.z, v.w);
    }
}

__global__ void __launch_bounds__(256) bias_cat_kernel(
    const float* __restrict__ bq, const float* __restrict__ bk,
    const float* __restrict__ bv, float* __restrict__ bqkv)
{
    int i = blockIdx.x * 256 + threadIdx.x;
    float val = (i < EMBED) ? bq[i] : (i < 2 * EMBED) ? bk[i - EMBED] : bv[i - 2 * EMBED];
    bqkv[i] = val;
}

// ---------------- host orchestration -----------------------------------------
extern "C" void kernel_launch(void* const* d_in, const int* in_sizes, int n_in,
                              void* d_out, int out_size)
{
    const float* x   = (const float*)d_in[0];
    const float* Wq  = (const float*)d_in[1];
    const float* bq  = (const float*)d_in[2];
    const float* Wk  = (const float*)d_in[3];
    const float* bk  = (const float*)d_in[4];
    const float* Wv  = (const float*)d_in[5];
    const float* bv  = (const float*)d_in[6];
    const float* Wo  = (const float*)d_in[7];
    const float* bo  = (const float*)d_in[8];
    const float* W1  = (const float*)d_in[9];
    const float* b1  = (const float*)d_in[10];
    const float* W2  = (const float*)d_in[11];
    const float* b2  = (const float*)d_in[12];
    const float* g1  = (const float*)d_in[13];
    const float* be1 = (const float*)d_in[14];
    const float* g2  = (const float*)d_in[15];
    const float* be2 = (const float*)d_in[16];
    float* out = (float*)d_out;

    __half *h, *qkv, *attnh, *ffh, *wqkv, *wo, *w1, *w2, *x1h;
    float *bqkv;
    cudaGetSymbolAddress((void**)&h,     g_h);
    cudaGetSymbolAddress((void**)&qkv,   g_qkv);
    cudaGetSymbolAddress((void**)&attnh, g_attnh);
    cudaGetSymbolAddress((void**)&x1h,   g_x1h);
    cudaGetSymbolAddress((void**)&ffh,   g_ffh);
    cudaGetSymbolAddress((void**)&wqkv,  g_wqkv);
    cudaGetSymbolAddress((void**)&wo,    g_wo);
    cudaGetSymbolAddress((void**)&w1,    g_w1);
    cudaGetSymbolAddress((void**)&w2,    g_w2);
    cudaGetSymbolAddress((void**)&bqkv,  g_bqkv);

    cudaFuncSetAttribute(gemm16_kernel<false,false,false,true>,
                         cudaFuncAttributeMaxDynamicSharedMemorySize, GSMEM);
    cudaFuncSetAttribute(gemm16_kernel<false,true,false,true>,
                         cudaFuncAttributeMaxDynamicSharedMemorySize, GSMEM);
    cudaFuncSetAttribute(gemm16_kernel<true,false,false,true>,
                         cudaFuncAttributeMaxDynamicSharedMemorySize, GSMEM);
    cudaFuncSetAttribute(gemm16_kernel<false,true,true,false>,
                         cudaFuncAttributeMaxDynamicSharedMemorySize, GSMEM);

    {
        dim3 g(256, 6);
        f2h_all_kernel<<<g, 256>>>(Wq, Wk, Wv, Wo, W1, W2, wqkv, wo, w1, w2);
        bias_cat_kernel<<<QKVDIM / 256, 256>>>(bq, bk, bv, bqkv);
    }

    // 1) h = LN1(x) -> fp16
    ln_kernel<<<N_NODES / 8, 256>>>(x, g1, be1, h);

    // 2) qkv = h @ Wqkv^T + bqkv (fp16 out)
    dim3 grdQKV(QKVDIM / BN, N_NODES / BM);   // (12, 512)
    gemm16_kernel<false,false,false,true><<<grdQKV, GTHREADS, GSMEM>>>(h, wqkv, bqkv, nullptr, qkv, EMBED, QKVDIM);

    // 3) per-node attention -> fp16
    attn_kernel<<<N_NODES / 8, 256>>>(qkv, attnh);

    // 4) x1h = x + attnh @ Wo^T + bo (fp16 out, fp32 residual in)
    dim3 grdE(EMBED / BN, N_NODES / BM);      // (4, 512)
    gemm16_kernel<false,true,false,true><<<grdE, GTHREADS, GSMEM>>>(attnh, wo, bo, x, x1h, EMBED, EMBED);

    // 5) h = LN2(x1h) -> fp16
    ln_h_kernel<<<N_NODES / 8, 256>>>(x1h, g2, be2, h);

    // 6) ffh = relu(h @ W1^T + b1) -> fp16
    dim3 grdF(FFDIM / BN, N_NODES / BM);      // (16, 512)
    gemm16_kernel<true,false,false,true><<<grdF, GTHREADS, GSMEM>>>(h, w1, b1, nullptr, ffh, EMBED, FFDIM);

    // 7) out = x1h + ffh @ W2^T + b2 (fp32 out, fp16 residual in)
    gemm16_kernel<false,true,true,false><<<grdE, GTHREADS, GSMEM>>>(ffh, w2, b2, x1h, out, FFDIM, EMBED);
}

// round 14
// speedup vs baseline: 1.2146x; 1.0720x over previous
#include <cuda_runtime.h>
#include <cuda_fp16.h>
#include <math.h>
#include <stdint.h>

#define N_NODES 65536
#define EMBED 512
#define FFDIM 2048
#define QKVDIM 1536
#define NHEADS 8
#define HDIM 64

// ---------------- scratch ----------------------------------------------------
__device__ __half g_h[(size_t)N_NODES * EMBED];
__device__ __half g_qkv[(size_t)N_NODES * QKVDIM];
__device__ __half g_attnh[(size_t)N_NODES * EMBED];
__device__ __half g_x1h[(size_t)N_NODES * EMBED];
__device__ __half g_ffh[(size_t)N_NODES * FFDIM];
__device__ __half g_wqkv[QKVDIM * EMBED];
__device__ float  g_bqkv[QKVDIM];
__device__ __half g_wo[EMBED * EMBED];
__device__ __half g_w1[FFDIM * EMBED];
__device__ __half g_w2[EMBED * FFDIM];

// ---------------- ptx helpers ------------------------------------------------
__device__ __forceinline__ uint32_t smem_u32(const void* p) {
    uint32_t a;
    asm("{ .reg .u64 t; cvta.to.shared.u64 t, %1; cvt.u32.u64 %0, t; }" : "=r"(a) : "l"(p));
    return a;
}
__device__ __forceinline__ void cp_async16(uint32_t saddr, const void* gaddr) {
    asm volatile("cp.async.cg.shared.global [%0], [%1], 16;\n" :: "r"(saddr), "l"(gaddr));
}
__device__ __forceinline__ void cpasync_mbar_arrive(uint32_t mbar) {
    asm volatile("cp.async.mbarrier.arrive.noinc.shared.b64 [%0];" :: "r"(mbar) : "memory");
}
__device__ __forceinline__ void mbar_init(uint32_t mbar, uint32_t cnt) {
    asm volatile("mbarrier.init.shared.b64 [%0], %1;" :: "r"(mbar), "r"(cnt) : "memory");
}
__device__ __forceinline__ void mbar_arrive(uint32_t mbar) {
    asm volatile("mbarrier.arrive.release.cta.shared.b64 _, [%0];" :: "r"(mbar) : "memory");
}
__device__ __forceinline__ void mbar_wait(uint32_t mbar, uint32_t parity) {
    asm volatile(
        "{\n\t.reg .pred P;\n\t"
        "WL%=:\n\t"
        "mbarrier.try_wait.parity.acquire.cta.shared::cta.b64 P, [%0], %1, 0x989680;\n\t"
        "@P bra WD%=;\n\t"
        "bra WL%=;\n\t"
        "WD%=:\n\t}"
        :: "r"(mbar), "r"(parity) : "memory");
}
__device__ __forceinline__ void ldm_x4(uint32_t* r, uint32_t addr) {
    asm volatile("ldmatrix.sync.aligned.m8n8.x4.shared.b16 {%0,%1,%2,%3}, [%4];"
                 : "=r"(r[0]), "=r"(r[1]), "=r"(r[2]), "=r"(r[3]) : "r"(addr));
}
__device__ __forceinline__ void mma16816(float* d, const uint32_t* a, const uint32_t* b) {
    asm volatile(
        "mma.sync.aligned.m16n8k16.row.col.f32.f16.f16.f32 "
        "{%0,%1,%2,%3}, {%4,%5,%6,%7}, {%8,%9}, {%0,%1,%2,%3};"
        : "+f"(d[0]), "+f"(d[1]), "+f"(d[2]), "+f"(d[3])
        : "r"(a[0]), "r"(a[1]), "r"(a[2]), "r"(a[3]), "r"(b[0]), "r"(b[1]));
}

// ---------------- HMMA fp16 GEMM (R8/R11 winner config) -----------------------
// CTA 128x128, BK=64 (ROWB=144 -> conflict-free ldmatrix), 3-stage cp.async
// pipeline with mbarriers (free-running). 8 warps (4x2), warp tile 32x64.
// Change vs R11: consumer-release (free-arrive) moved to right after the last
// ldmatrix of the chunk (mbarrier.arrive release semantics cover the prior
// loads), freeing the stage before the final MMA block executes.
#define BM 128
#define BN 128
#define BK 64
#define ROWB 144
#define TILEB (128 * ROWB)           // 18432 per tile (A or B)
#define STAGEB (2 * TILEB)           // 36864 per stage
#define GSMEM (64 + 3 * STAGEB)      // 110656

template<bool RELU, bool HASRES, bool RESHALF, bool OUTHALF>
__global__ void __launch_bounds__(256) gemm16_kernel(
    const __half* __restrict__ A, const __half* __restrict__ B,
    const float* __restrict__ bias, const void* __restrict__ resv,
    void* __restrict__ Cv, int K, int M)
{
    extern __shared__ __align__(16) char smem[];
    const uint32_t sb = smem_u32(smem);
    const uint32_t tb = sb + 64;
    const int tid = threadIdx.x;
    const int lane = tid & 31;
    const int wid = tid >> 5;
    const int wm = wid & 3;
    const int wn = wid >> 2;
    const int bm = blockIdx.y * BM;
    const int bn = blockIdx.x * BN;

    if (tid == 0) {
#pragma unroll
        for (int s = 0; s < 3; s++) {
            mbar_init(sb + s * 8, 256);        // full[s]
            mbar_init(sb + 24 + s * 8, 256);   // free[s]
        }
    }
    __syncthreads();

    uint32_t soff[4];
    const __half* agp[4];
    const __half* bgp[4];
#pragma unroll
    for (int i = 0; i < 4; i++) {
        int seg = tid + i * 256;
        int r = seg >> 3, c = seg & 7;
        soff[i] = r * ROWB + c * 16;
        agp[i] = A + (size_t)(bm + r) * K + c * 8;
        bgp[i] = B + (size_t)(bn + r) * K + c * 8;
    }

    uint32_t a_off[2], b_off[4];
#pragma unroll
    for (int mf = 0; mf < 2; mf++)
        a_off[mf] = (wm * 32 + mf * 16 + (lane & 15)) * ROWB + ((lane >> 4) * 16);
#pragma unroll
    for (int p = 0; p < 4; p++)
        b_off[p] = (wn * 64 + p * 16 + ((lane >> 4) << 3) + (lane & 7)) * ROWB
                 + (((lane >> 3) & 1) * 16);

    float acc[2][8][4];
#pragma unroll
    for (int i = 0; i < 2; i++)
#pragma unroll
        for (int j = 0; j < 8; j++)
#pragma unroll
            for (int t = 0; t < 4; t++) acc[i][j][t] = 0.f;

    const int NC = K >> 6;

#pragma unroll
    for (int pc = 0; pc < 2; pc++) {
        const uint32_t base = tb + pc * STAGEB;
        const int ko = pc * BK;
#pragma unroll
        for (int i = 0; i < 4; i++) {
            cp_async16(base + soff[i], agp[i] + ko);
            cp_async16(base + TILEB + soff[i], bgp[i] + ko);
        }
        cpasync_mbar_arrive(sb + pc * 8);
    }

    int st = 0;
    uint32_t pful = 0;
    int pt = 2;
    uint32_t wfree = 1;

#pragma unroll 1
    for (int chunk = 0; chunk < NC; chunk++) {
        const int pc = chunk + 2;
        if (pc < NC) {
            if (pc >= 3) mbar_wait(sb + 24 + pt * 8, wfree);
            const uint32_t base = tb + pt * STAGEB;
            const int ko = pc * BK;
#pragma unroll
            for (int i = 0; i < 4; i++) {
                cp_async16(base + soff[i], agp[i] + ko);
                cp_async16(base + TILEB + soff[i], bgp[i] + ko);
            }
            cpasync_mbar_arrive(sb + pt * 8);
            if (pt == 2) { pt = 0; wfree ^= 1u; } else pt++;
        }

        mbar_wait(sb + st * 8, pful);
        const uint32_t ab = tb + st * STAGEB;
        const uint32_t bb = ab + TILEB;
#pragma unroll
        for (int ks = 0; ks < 4; ks++) {
            uint32_t afr[2][4], bfr[4][4];
            ldm_x4(afr[0], ab + a_off[0] + ks * 32);
            ldm_x4(afr[1], ab + a_off[1] + ks * 32);
#pragma unroll
            for (int p = 0; p < 4; p++) ldm_x4(bfr[p], bb + b_off[p] + ks * 32);
            // after the LAST ldmatrix of this chunk, release the stage:
            // arrive.release orders all prior shared-memory loads.
            if (ks == 3) mbar_arrive(sb + 24 + st * 8);
#pragma unroll
            for (int mf = 0; mf < 2; mf++)
#pragma unroll
                for (int nf = 0; nf < 8; nf++)
                    mma16816(acc[mf][nf], afr[mf], &bfr[nf >> 1][(nf & 1) * 2]);
        }
        if (st == 2) { st = 0; pful ^= 1u; } else st++;
    }

    // epilogue
    const int mrow = bm + wm * 32 + (lane >> 2);
    const int ncol = bn + wn * 64 + (lane & 3) * 2;
#pragma unroll
    for (int mf = 0; mf < 2; mf++) {
#pragma unroll
        for (int half8 = 0; half8 < 2; half8++) {
            const int row = mrow + mf * 16 + half8 * 8;
#pragma unroll
            for (int nf = 0; nf < 8; nf++) {
                const int col = ncol + nf * 8;
                float c0 = acc[mf][nf][half8 * 2 + 0];
                float c1 = acc[mf][nf][half8 * 2 + 1];
                float2 b2 = *(const float2*)&bias[col];
                c0 += b2.x; c1 += b2.y;
                if (RELU) { c0 = fmaxf(c0, 0.f); c1 = fmaxf(c1, 0.f); }
                if (HASRES) {
                    if (RESHALF) {
                        __half2 r2 = *(const __half2*)((const __half*)resv + (size_t)row * M + col);
                        float2 rf = __half22float2(r2);
                        c0 += rf.x; c1 += rf.y;
                    } else {
                        float2 r2 = *(const float2*)((const float*)resv + (size_t)row * M + col);
                        c0 += r2.x; c1 += r2.y;
                    }
                }
                if (OUTHALF) {
                    *(__half2*)((__half*)Cv + (size_t)row * M + col) =
                        __floats2half2_rn(c0, c1);
                } else {
                    *(float2*)((float*)Cv + (size_t)row * M + col) =
                        make_float2(c0, c1);
                }
            }
        }
    }
}

// ---------------- LayerNorm (fp32 in) -> fp16, warp-per-row, 16 rows/blk -----
__global__ void __launch_bounds__(512) ln_kernel(
    const float* __restrict__ x, const float* __restrict__ gamma,
    const float* __restrict__ beta, __half* __restrict__ y)
{
    const int w = threadIdx.x >> 5, lane = threadIdx.x & 31;
    const size_t row = (size_t)blockIdx.x * 16 + w;
    const float4* xp = (const float4*)(x + row * EMBED);
    float4 v[4];
    float s = 0.f, s2 = 0.f;
#pragma unroll
    for (int k = 0; k < 4; k++) {
        v[k] = xp[k * 32 + lane];
        s  += v[k].x + v[k].y + v[k].z + v[k].w;
        s2 += v[k].x*v[k].x + v[k].y*v[k].y + v[k].z*v[k].z + v[k].w*v[k].w;
    }
#pragma unroll
    for (int o = 16; o > 0; o >>= 1) {
        s  += __shfl_xor_sync(0xffffffffu, s,  o);
        s2 += __shfl_xor_sync(0xffffffffu, s2, o);
    }
    const float mu = s * (1.0f / EMBED);
    const float inv = rsqrtf(s2 * (1.0f / EMBED) - mu * mu + 1e-5f);
    __half2* yp = (__half2*)(y + row * EMBED);
#pragma unroll
    for (int k = 0; k < 4; k++) {
        float4 g4 = ((const float4*)gamma)[k * 32 + lane];
        float4 b4 = ((const float4*)beta)[k * 32 + lane];
        yp[(k * 32 + lane) * 2] =
            __floats2half2_rn((v[k].x - mu) * inv * g4.x + b4.x,
                              (v[k].y - mu) * inv * g4.y + b4.y);
        yp[(k * 32 + lane) * 2 + 1] =
            __floats2half2_rn((v[k].z - mu) * inv * g4.z + b4.z,
                              (v[k].w - mu) * inv * g4.w + b4.w);
    }
}

// ---------------- LayerNorm (fp16 in) -> fp16, warp-per-row, 16 rows/blk -----
__global__ void __launch_bounds__(512) ln_h_kernel(
    const __half* __restrict__ x, const float* __restrict__ gamma,
    const float* __restrict__ beta, __half* __restrict__ y)
{
    const int w = threadIdx.x >> 5, lane = threadIdx.x & 31;
    const size_t row = (size_t)blockIdx.x * 16 + w;
    const uint4* xp = (const uint4*)(x + row * EMBED);
    uint4 raw[2];
    float f[16];
    float s = 0.f, s2 = 0.f;
#pragma unroll
    for (int k = 0; k < 2; k++) {
        raw[k] = xp[k * 32 + lane];
        const __half2* hp = (const __half2*)&raw[k];
#pragma unroll
        for (int j = 0; j < 4; j++) {
            float2 fj = __half22float2(hp[j]);
            f[k * 8 + j * 2]     = fj.x;
            f[k * 8 + j * 2 + 1] = fj.y;
            s  += fj.x + fj.y;
            s2 += fj.x * fj.x + fj.y * fj.y;
        }
    }
#pragma unroll
    for (int o = 16; o > 0; o >>= 1) {
        s  += __shfl_xor_sync(0xffffffffu, s,  o);
        s2 += __shfl_xor_sync(0xffffffffu, s2, o);
    }
    const float mu = s * (1.0f / EMBED);
    const float inv = rsqrtf(s2 * (1.0f / EMBED) - mu * mu + 1e-5f);
    __half2* yp = (__half2*)(y + row * EMBED);
#pragma unroll
    for (int k = 0; k < 2; k++) {
        const int base4 = (k * 32 + lane) * 2;
#pragma unroll
        for (int q = 0; q < 2; q++) {
            float4 g4 = ((const float4*)gamma)[base4 + q];
            float4 b4 = ((const float4*)beta)[base4 + q];
            yp[(base4 + q) * 2] =
                __floats2half2_rn((f[k*8 + q*4 + 0] - mu) * inv * g4.x + b4.x,
                                  (f[k*8 + q*4 + 1] - mu) * inv * g4.y + b4.y);
            yp[(base4 + q) * 2 + 1] =
                __floats2half2_rn((f[k*8 + q*4 + 2] - mu) * inv * g4.z + b4.z,
                                  (f[k*8 + q*4 + 3] - mu) * inv * g4.w + b4.w);
        }
    }
}

// ---------------- per-node attention, warp-per-node ---------------------------
__global__ void __launch_bounds__(256) attn_kernel(
    const __half* __restrict__ qkv, __half* __restrict__ out)
{
    const int w = threadIdx.x >> 5, lane = threadIdx.x & 31;
    const size_t node = (size_t)blockIdx.x * 8 + w;

    __shared__ __half s[8][QKVDIM];
    __shared__ float sa[8][64];

    const uint4* rp = (const uint4*)(qkv + node * QKVDIM);
    uint4* sp = (uint4*)s[w];
#pragma unroll
    for (int i = 0; i < 6; i++) sp[i * 32 + lane] = rp[i * 32 + lane];
    __syncwarp();

    const __half* sq = s[w];
    const __half* sk = s[w] + EMBED;
    const __half* sv = s[w] + 2 * EMBED;

    float sc[2];
#pragma unroll
    for (int pi = 0; pi < 2; pi++) {
        const int p = lane + pi * 32;
        const int h = p >> 3, g = p & 7;
        const __half2* qh = (const __half2*)(sq + h * HDIM);
        const __half2* kh = (const __half2*)(sk + g * HDIM);
        float a = 0.f;
#pragma unroll
        for (int dd = 0; dd < 32; dd++) {
            const int d = (dd + g * 4 + (h & 3) * 8) & 31;
            float2 a2 = __half22float2(qh[d]);
            float2 b2 = __half22float2(kh[d]);
            a += a2.x * b2.x + a2.y * b2.y;
        }
        sc[pi] = a * 0.125f;
    }

#pragma unroll
    for (int pi = 0; pi < 2; pi++) {
        float m = sc[pi];
#pragma unroll
        for (int o = 4; o > 0; o >>= 1)
            m = fmaxf(m, __shfl_xor_sync(0xffffffffu, m, o));
        float e = expf(sc[pi] - m);
        float ssum = e;
#pragma unroll
        for (int o = 4; o > 0; o >>= 1)
            ssum += __shfl_xor_sync(0xffffffffu, ssum, o);
        sa[w][lane + pi * 32] = e / ssum;
    }
    __syncwarp();

    __half* op = out + node * EMBED;
#pragma unroll
    for (int h = 0; h < NHEADS; h++) {
        float o0 = 0.f, o1 = 0.f;
#pragma unroll
        for (int g = 0; g < 8; g++) {
            const float a = sa[w][h * 8 + g];
            o0 += a * __half2float(sv[g * HDIM + lane]);
            o1 += a * __half2float(sv[g * HDIM + 32 + lane]);
        }
        op[h * HDIM + lane]      = __float2half(o0);
        op[h * HDIM + 32 + lane] = __float2half(o1);
    }
}

// ---------------- weight + bias conversion, one launch ------------------------
__global__ void __launch_bounds__(256) f2h_all_kernel(
    const float* __restrict__ Wq, const float* __restrict__ Wk,
    const float* __restrict__ Wv, const float* __restrict__ Wo,
    const float* __restrict__ W1, const float* __restrict__ W2,
    const float* __restrict__ bq, const float* __restrict__ bk,
    const float* __restrict__ bv,
    __half* __restrict__ wqkv, __half* __restrict__ wo,
    __half* __restrict__ w1, __half* __restrict__ w2,
    float* __restrict__ bqkv)
{
    int y = blockIdx.y;
    if (y == 6) {   // bias concat: 1536 floats
        for (int i = blockIdx.x * blockDim.x + threadIdx.x; i < QKVDIM;
             i += gridDim.x * blockDim.x) {
            float val = (i < EMBED) ? bq[i]
                      : (i < 2 * EMBED) ? bk[i - EMBED] : bv[i - 2 * EMBED];
            bqkv[i] = val;
        }
        return;
    }
    const float* s; __half* d; int n4;
    if      (y == 0) { s = Wq; d = wqkv;                 n4 = EMBED*EMBED/4; }
    else if (y == 1) { s = Wk; d = wqkv + EMBED*EMBED;   n4 = EMBED*EMBED/4; }
    else if (y == 2) { s = Wv; d = wqkv + 2*EMBED*EMBED; n4 = EMBED*EMBED/4; }
    else if (y == 3) { s = Wo; d = wo;                   n4 = EMBED*EMBED/4; }
    else if (y == 4) { s = W1; d = w1;                   n4 = FFDIM*EMBED/4; }
    else             { s = W2; d = w2;                   n4 = FFDIM*EMBED/4; }
    for (int i = blockIdx.x * blockDim.x + threadIdx.x; i < n4; i += gridDim.x * blockDim.x) {
        float4 v = ((const float4*)s)[i];
        __half2* dp = (__half2*)d + i * 2;
        dp[0] = __floats2half2_rn(v.x, v.y);
        dp[1] = __floats2half2_rn(v.z, v.w);
    }
}

// ---------------- host orchestration -----------------------------------------
extern "C" void kernel_launch(void* const* d_in, const int* in_sizes, int n_in,
                              void* d_out, int out_size)
{
    const float* x   = (const float*)d_in[0];
    const float* Wq  = (const float*)d_in[1];
    const float* bq  = (const float*)d_in[2];
    const float* Wk  = (const float*)d_in[3];
    const float* bk  = (const float*)d_in[4];
    const float* Wv  = (const float*)d_in[5];
    const float* bv  = (const float*)d_in[6];
    const float* Wo  = (const float*)d_in[7];
    const float* bo  = (const float*)d_in[8];
    const float* W1  = (const float*)d_in[9];
    const float* b1  = (const float*)d_in[10];
    const float* W2  = (const float*)d_in[11];
    const float* b2  = (const float*)d_in[12];
    const float* g1  = (const float*)d_in[13];
    const float* be1 = (const float*)d_in[14];
    const float* g2  = (const float*)d_in[15];
    const float* be2 = (const float*)d_in[16];
    float* out = (float*)d_out;

    __half *h, *qkv, *attnh, *ffh, *wqkv, *wo, *w1, *w2, *x1h;
    float *bqkv;
    cudaGetSymbolAddress((void**)&h,     g_h);
    cudaGetSymbolAddress((void**)&qkv,   g_qkv);
    cudaGetSymbolAddress((void**)&attnh, g_attnh);
    cudaGetSymbolAddress((void**)&x1h,   g_x1h);
    cudaGetSymbolAddress((void**)&ffh,   g_ffh);
    cudaGetSymbolAddress((void**)&wqkv,  g_wqkv);
    cudaGetSymbolAddress((void**)&wo,    g_wo);
    cudaGetSymbolAddress((void**)&w1,    g_w1);
    cudaGetSymbolAddress((void**)&w2,    g_w2);
    cudaGetSymbolAddress((void**)&bqkv,  g_bqkv);

    cudaFuncSetAttribute(gemm16_kernel<false,false,false,true>,
                         cudaFuncAttributeMaxDynamicSharedMemorySize, GSMEM);
    cudaFuncSetAttribute(gemm16_kernel<false,true,false,true>,
                         cudaFuncAttributeMaxDynamicSharedMemorySize, GSMEM);
    cudaFuncSetAttribute(gemm16_kernel<true,false,false,true>,
                         cudaFuncAttributeMaxDynamicSharedMemorySize, GSMEM);
    cudaFuncSetAttribute(gemm16_kernel<false,true,true,false>,
                         cudaFuncAttributeMaxDynamicSharedMemorySize, GSMEM);

    {
        dim3 g(256, 7);   // y=0..5 weights, y=6 bias concat
        f2h_all_kernel<<<g, 256>>>(Wq, Wk, Wv, Wo, W1, W2, bq, bk, bv,
                                   wqkv, wo, w1, w2, bqkv);
    }

    // 1) h = LN1(x) -> fp16
    ln_kernel<<<N_NODES / 16, 512>>>(x, g1, be1, h);

    // 2) qkv = h @ Wqkv^T + bqkv (fp16 out)
    dim3 grdQKV(QKVDIM / BN, N_NODES / BM);   // (12, 512)
    gemm16_kernel<false,false,false,true><<<grdQKV, 256, GSMEM>>>(h, wqkv, bqkv, nullptr, qkv, EMBED, QKVDIM);

    // 3) per-node attention -> fp16
    attn_kernel<<<N_NODES / 8, 256>>>(qkv, attnh);

    // 4) x1h = x + attnh @ Wo^T + bo (fp16 out, fp32 residual in)
    dim3 grdE(EMBED / BN, N_NODES / BM);      // (4, 512)
    gemm16_kernel<false,true,false,true><<<grdE, 256, GSMEM>>>(attnh, wo, bo, x, x1h, EMBED, EMBED);

    // 5) h = LN2(x1h) -> fp16
    ln_h_kernel<<<N_NODES / 16, 512>>>(x1h, g2, be2, h);

    // 6) ffh = relu(h @ W1^T + b1) -> fp16
    dim3 grdF(FFDIM / BN, N_NODES / BM);      // (16, 512)
    gemm16_kernel<true,false,false,true><<<grdF, 256, GSMEM>>>(h, w1, b1, nullptr, ffh, EMBED, FFDIM);

    // 7) out = x1h + ffh @ W2^T + b2 (fp32 out, fp16 residual in)
    gemm16_kernel<false,true,true,false><<<grdE, 256, GSMEM>>>(ffh, w2, b2, x1h, out, FFDIM, EMBED);
}

// round 15
// speedup vs baseline: 1.2614x; 1.0385x over previous
#include <cuda_runtime.h>
#include <cuda_fp16.h>
#include <math.h>
#include <stdint.h>

#define N_NODES 65536
#define EMBED 512
#define FFDIM 2048
#define QKVDIM 1536
#define NHEADS 8
#define HDIM 64

// ---------------- scratch ----------------------------------------------------
__device__ __half g_h[(size_t)N_NODES * EMBED];
__device__ __half g_qkv[(size_t)N_NODES * QKVDIM];
__device__ __half g_attnh[(size_t)N_NODES * EMBED];
__device__ __half g_x1h[(size_t)N_NODES * EMBED];
__device__ __half g_ffh[(size_t)N_NODES * FFDIM];
__device__ __half g_wqkv[QKVDIM * EMBED];
__device__ float  g_bqkv[QKVDIM];
__device__ __half g_wo[EMBED * EMBED];
__device__ __half g_w1[FFDIM * EMBED];
__device__ __half g_w2[EMBED * FFDIM];

// ---------------- ptx helpers ------------------------------------------------
__device__ __forceinline__ uint32_t smem_u32(const void* p) {
    uint32_t a;
    asm("{ .reg .u64 t; cvta.to.shared.u64 t, %1; cvt.u32.u64 %0, t; }" : "=r"(a) : "l"(p));
    return a;
}
__device__ __forceinline__ void cp_async16(uint32_t saddr, const void* gaddr) {
    asm volatile("cp.async.cg.shared.global [%0], [%1], 16;\n" :: "r"(saddr), "l"(gaddr));
}
__device__ __forceinline__ void cpasync_mbar_arrive(uint32_t mbar) {
    asm volatile("cp.async.mbarrier.arrive.noinc.shared.b64 [%0];" :: "r"(mbar) : "memory");
}
__device__ __forceinline__ void mbar_init(uint32_t mbar, uint32_t cnt) {
    asm volatile("mbarrier.init.shared.b64 [%0], %1;" :: "r"(mbar), "r"(cnt) : "memory");
}
__device__ __forceinline__ void mbar_arrive(uint32_t mbar) {
    asm volatile("mbarrier.arrive.release.cta.shared.b64 _, [%0];" :: "r"(mbar) : "memory");
}
__device__ __forceinline__ void mbar_wait(uint32_t mbar, uint32_t parity) {
    asm volatile(
        "{\n\t.reg .pred P;\n\t"
        "WL%=:\n\t"
        "mbarrier.try_wait.parity.acquire.cta.shared::cta.b64 P, [%0], %1, 0x989680;\n\t"
        "@P bra WD%=;\n\t"
        "bra WL%=;\n\t"
        "WD%=:\n\t}"
        :: "r"(mbar), "r"(parity) : "memory");
}
__device__ __forceinline__ void ldm_x4(uint32_t* r, uint32_t addr) {
    asm volatile("ldmatrix.sync.aligned.m8n8.x4.shared.b16 {%0,%1,%2,%3}, [%4];"
                 : "=r"(r[0]), "=r"(r[1]), "=r"(r[2]), "=r"(r[3]) : "r"(addr));
}
__device__ __forceinline__ void mma16816(float* d, const uint32_t* a, const uint32_t* b) {
    asm volatile(
        "mma.sync.aligned.m16n8k16.row.col.f32.f16.f16.f32 "
        "{%0,%1,%2,%3}, {%4,%5,%6,%7}, {%8,%9}, {%0,%1,%2,%3};"
        : "+f"(d[0]), "+f"(d[1]), "+f"(d[2]), "+f"(d[3])
        : "r"(a[0]), "r"(a[1]), "r"(a[2]), "r"(a[3]), "r"(b[0]), "r"(b[1]));
}

// ---------------- HMMA fp16 GEMM (R8/R11/R14 winner config) -------------------
#define BM 128
#define BN 128
#define BK 64
#define ROWB 144
#define TILEB (128 * ROWB)           // 18432 per tile (A or B)
#define STAGEB (2 * TILEB)           // 36864 per stage
#define GSMEM (64 + 3 * STAGEB)      // 110656

template<bool RELU, bool HASRES, bool RESHALF, bool OUTHALF>
__global__ void __launch_bounds__(256) gemm16_kernel(
    const __half* __restrict__ A, const __half* __restrict__ B,
    const float* __restrict__ bias, const void* __restrict__ resv,
    void* __restrict__ Cv, int K, int M)
{
    extern __shared__ __align__(16) char smem[];
    const uint32_t sb = smem_u32(smem);
    const uint32_t tb = sb + 64;
    const int tid = threadIdx.x;
    const int lane = tid & 31;
    const int wid = tid >> 5;
    const int wm = wid & 3;
    const int wn = wid >> 2;
    const int bm = blockIdx.y * BM;
    const int bn = blockIdx.x * BN;

    if (tid == 0) {
#pragma unroll
        for (int s = 0; s < 3; s++) {
            mbar_init(sb + s * 8, 256);
            mbar_init(sb + 24 + s * 8, 256);
        }
    }
    __syncthreads();

    uint32_t soff[4];
    const __half* agp[4];
    const __half* bgp[4];
#pragma unroll
    for (int i = 0; i < 4; i++) {
        int seg = tid + i * 256;
        int r = seg >> 3, c = seg & 7;
        soff[i] = r * ROWB + c * 16;
        agp[i] = A + (size_t)(bm + r) * K + c * 8;
        bgp[i] = B + (size_t)(bn + r) * K + c * 8;
    }

    uint32_t a_off[2], b_off[4];
#pragma unroll
    for (int mf = 0; mf < 2; mf++)
        a_off[mf] = (wm * 32 + mf * 16 + (lane & 15)) * ROWB + ((lane >> 4) * 16);
#pragma unroll
    for (int p = 0; p < 4; p++)
        b_off[p] = (wn * 64 + p * 16 + ((lane >> 4) << 3) + (lane & 7)) * ROWB
                 + (((lane >> 3) & 1) * 16);

    float acc[2][8][4];
#pragma unroll
    for (int i = 0; i < 2; i++)
#pragma unroll
        for (int j = 0; j < 8; j++)
#pragma unroll
            for (int t = 0; t < 4; t++) acc[i][j][t] = 0.f;

    const int NC = K >> 6;

#pragma unroll
    for (int pc = 0; pc < 2; pc++) {
        const uint32_t base = tb + pc * STAGEB;
        const int ko = pc * BK;
#pragma unroll
        for (int i = 0; i < 4; i++) {
            cp_async16(base + soff[i], agp[i] + ko);
            cp_async16(base + TILEB + soff[i], bgp[i] + ko);
        }
        cpasync_mbar_arrive(sb + pc * 8);
    }

    int st = 0;
    uint32_t pful = 0;
    int pt = 2;
    uint32_t wfree = 1;

#pragma unroll 1
    for (int chunk = 0; chunk < NC; chunk++) {
        const int pc = chunk + 2;
        if (pc < NC) {
            if (pc >= 3) mbar_wait(sb + 24 + pt * 8, wfree);
            const uint32_t base = tb + pt * STAGEB;
            const int ko = pc * BK;
#pragma unroll
            for (int i = 0; i < 4; i++) {
                cp_async16(base + soff[i], agp[i] + ko);
                cp_async16(base + TILEB + soff[i], bgp[i] + ko);
            }
            cpasync_mbar_arrive(sb + pt * 8);
            if (pt == 2) { pt = 0; wfree ^= 1u; } else pt++;
        }

        mbar_wait(sb + st * 8, pful);
        const uint32_t ab = tb + st * STAGEB;
        const uint32_t bb = ab + TILEB;
#pragma unroll
        for (int ks = 0; ks < 4; ks++) {
            uint32_t afr[2][4], bfr[4][4];
            ldm_x4(afr[0], ab + a_off[0] + ks * 32);
            ldm_x4(afr[1], ab + a_off[1] + ks * 32);
#pragma unroll
            for (int p = 0; p < 4; p++) ldm_x4(bfr[p], bb + b_off[p] + ks * 32);
            if (ks == 3) mbar_arrive(sb + 24 + st * 8);
#pragma unroll
            for (int mf = 0; mf < 2; mf++)
#pragma unroll
                for (int nf = 0; nf < 8; nf++)
                    mma16816(acc[mf][nf], afr[mf], &bfr[nf >> 1][(nf & 1) * 2]);
        }
        if (st == 2) { st = 0; pful ^= 1u; } else st++;
    }

    const int mrow = bm + wm * 32 + (lane >> 2);
    const int ncol = bn + wn * 64 + (lane & 3) * 2;
#pragma unroll
    for (int mf = 0; mf < 2; mf++) {
#pragma unroll
        for (int half8 = 0; half8 < 2; half8++) {
            const int row = mrow + mf * 16 + half8 * 8;
#pragma unroll
            for (int nf = 0; nf < 8; nf++) {
                const int col = ncol + nf * 8;
                float c0 = acc[mf][nf][half8 * 2 + 0];
                float c1 = acc[mf][nf][half8 * 2 + 1];
                float2 b2 = *(const float2*)&bias[col];
                c0 += b2.x; c1 += b2.y;
                if (RELU) { c0 = fmaxf(c0, 0.f); c1 = fmaxf(c1, 0.f); }
                if (HASRES) {
                    if (RESHALF) {
                        __half2 r2 = *(const __half2*)((const __half*)resv + (size_t)row * M + col);
                        float2 rf = __half22float2(r2);
                        c0 += rf.x; c1 += rf.y;
                    } else {
                        float2 r2 = *(const float2*)((const float*)resv + (size_t)row * M + col);
                        c0 += r2.x; c1 += r2.y;
                    }
                }
                if (OUTHALF) {
                    *(__half2*)((__half*)Cv + (size_t)row * M + col) =
                        __floats2half2_rn(c0, c1);
                } else {
                    *(float2*)((float*)Cv + (size_t)row * M + col) =
                        make_float2(c0, c1);
                }
            }
        }
    }
}

// ---------------- LayerNorm (fp32 in) -> fp16, warp-per-row, 16 rows/blk -----
__global__ void __launch_bounds__(512) ln_kernel(
    const float* __restrict__ x, const float* __restrict__ gamma,
    const float* __restrict__ beta, __half* __restrict__ y)
{
    const int w = threadIdx.x >> 5, lane = threadIdx.x & 31;
    const size_t row = (size_t)blockIdx.x * 16 + w;
    const float4* xp = (const float4*)(x + row * EMBED);
    float4 v[4];
    float s = 0.f, s2 = 0.f;
#pragma unroll
    for (int k = 0; k < 4; k++) {
        v[k] = xp[k * 32 + lane];
        s  += v[k].x + v[k].y + v[k].z + v[k].w;
        s2 += v[k].x*v[k].x + v[k].y*v[k].y + v[k].z*v[k].z + v[k].w*v[k].w;
    }
#pragma unroll
    for (int o = 16; o > 0; o >>= 1) {
        s  += __shfl_xor_sync(0xffffffffu, s,  o);
        s2 += __shfl_xor_sync(0xffffffffu, s2, o);
    }
    const float mu = s * (1.0f / EMBED);
    const float inv = rsqrtf(s2 * (1.0f / EMBED) - mu * mu + 1e-5f);
    __half2* yp = (__half2*)(y + row * EMBED);
#pragma unroll
    for (int k = 0; k < 4; k++) {
        float4 g4 = ((const float4*)gamma)[k * 32 + lane];
        float4 b4 = ((const float4*)beta)[k * 32 + lane];
        yp[(k * 32 + lane) * 2] =
            __floats2half2_rn((v[k].x - mu) * inv * g4.x + b4.x,
                              (v[k].y - mu) * inv * g4.y + b4.y);
        yp[(k * 32 + lane) * 2 + 1] =
            __floats2half2_rn((v[k].z - mu) * inv * g4.z + b4.z,
                              (v[k].w - mu) * inv * g4.w + b4.w);
    }
}

// ---------------- LayerNorm (fp16 in) -> fp16, warp-per-row, 16 rows/blk -----
__global__ void __launch_bounds__(512) ln_h_kernel(
    const __half* __restrict__ x, const float* __restrict__ gamma,
    const float* __restrict__ beta, __half* __restrict__ y)
{
    const int w = threadIdx.x >> 5, lane = threadIdx.x & 31;
    const size_t row = (size_t)blockIdx.x * 16 + w;
    const uint4* xp = (const uint4*)(x + row * EMBED);
    uint4 raw[2];
    float f[16];
    float s = 0.f, s2 = 0.f;
#pragma unroll
    for (int k = 0; k < 2; k++) {
        raw[k] = xp[k * 32 + lane];
        const __half2* hp = (const __half2*)&raw[k];
#pragma unroll
        for (int j = 0; j < 4; j++) {
            float2 fj = __half22float2(hp[j]);
            f[k * 8 + j * 2]     = fj.x;
            f[k * 8 + j * 2 + 1] = fj.y;
            s  += fj.x + fj.y;
            s2 += fj.x * fj.x + fj.y * fj.y;
        }
    }
#pragma unroll
    for (int o = 16; o > 0; o >>= 1) {
        s  += __shfl_xor_sync(0xffffffffu, s,  o);
        s2 += __shfl_xor_sync(0xffffffffu, s2, o);
    }
    const float mu = s * (1.0f / EMBED);
    const float inv = rsqrtf(s2 * (1.0f / EMBED) - mu * mu + 1e-5f);
    __half2* yp = (__half2*)(y + row * EMBED);
#pragma unroll
    for (int k = 0; k < 2; k++) {
        const int base4 = (k * 32 + lane) * 2;
#pragma unroll
        for (int q = 0; q < 2; q++) {
            float4 g4 = ((const float4*)gamma)[base4 + q];
            float4 b4 = ((const float4*)beta)[base4 + q];
            yp[(base4 + q) * 2] =
                __floats2half2_rn((f[k*8 + q*4 + 0] - mu) * inv * g4.x + b4.x,
                                  (f[k*8 + q*4 + 1] - mu) * inv * g4.y + b4.y);
            yp[(base4 + q) * 2 + 1] =
                __floats2half2_rn((f[k*8 + q*4 + 2] - mu) * inv * g4.z + b4.z,
                                  (f[k*8 + q*4 + 3] - mu) * inv * g4.w + b4.w);
        }
    }
}

// ---------------- per-node attention, warp-per-node, vectorized LDS ----------
// Score phase: LDS.128 octet loads with rotation j=(o+g)&7 — conflict-free per
// quarter-warp (one h-group; distinct octets over g for q, distinct rows+octets
// for k). Output phase: V d-pair hoisted to registers (8 half2 loads), all 8
// heads reuse them; score reads are warp-uniform broadcasts.
__device__ __forceinline__ float dot8(uint4 a, uint4 b) {
    const __half2* ah = (const __half2*)&a;
    const __half2* bh = (const __half2*)&b;
    float r = 0.f;
#pragma unroll
    for (int j = 0; j < 4; j++) {
        float2 af = __half22float2(ah[j]);
        float2 bf = __half22float2(bh[j]);
        r += af.x * bf.x + af.y * bf.y;
    }
    return r;
}

__global__ void __launch_bounds__(256) attn_kernel(
    const __half* __restrict__ qkv, __half* __restrict__ out)
{
    const int w = threadIdx.x >> 5, lane = threadIdx.x & 31;
    const size_t node = (size_t)blockIdx.x * 8 + w;

    __shared__ __half s[8][QKVDIM];   // 24 KB
    __shared__ float sa[8][64];       // 2 KB

    // load q|k|v row: 192 uint4, 6 per lane
    const uint4* rp = (const uint4*)(qkv + node * QKVDIM);
    uint4* sp = (uint4*)s[w];
#pragma unroll
    for (int i = 0; i < 6; i++) sp[i * 32 + lane] = rp[i * 32 + lane];
    __syncwarp();

    const uint4* q4 = (const uint4*)(s[w]);            // q rows: 8 uint4 each
    const uint4* k4 = (const uint4*)(s[w] + EMBED);    // k rows
    const __half2* sv2 = (const __half2*)(s[w] + 2 * EMBED);

    // scores: lane covers pairs (h0, g) and (h0+4, g); h0 = lane>>3, g = lane&7
    const int h0 = lane >> 3, g = lane & 7;
    float a0 = 0.f, a1 = 0.f;
#pragma unroll
    for (int o = 0; o < 8; o++) {
        const int j = (o + g) & 7;
        uint4 kv = k4[g * 8 + j];
        uint4 q0 = q4[h0 * 8 + j];
        uint4 q1 = q4[(h0 + 4) * 8 + j];
        a0 += dot8(q0, kv);
        a1 += dot8(q1, kv);
    }
    float sc[2] = { a0 * 0.125f, a1 * 0.125f };

    // softmax over 8-lane groups (lanes h0*8..h0*8+7 share h)
#pragma unroll
    for (int pi = 0; pi < 2; pi++) {
        float m = sc[pi];
#pragma unroll
        for (int o = 4; o > 0; o >>= 1)
            m = fmaxf(m, __shfl_xor_sync(0xffffffffu, m, o));
        float e = expf(sc[pi] - m);
        float ssum = e;
#pragma unroll
        for (int o = 4; o > 0; o >>= 1)
            ssum += __shfl_xor_sync(0xffffffffu, ssum, o);
        sa[w][lane + pi * 32] = e / ssum;
    }
    __syncwarp();

    // hoist V d-pair (d = 2*lane, 2*lane+1) for all g into registers
    float2 vreg[8];
#pragma unroll
    for (int gg = 0; gg < 8; gg++)
        vreg[gg] = __half22float2(sv2[gg * 32 + lane]);

    // out[h][2*lane .. 2*lane+1] = sum_g a[h][g] * vreg[g]
    __half2* op2 = (__half2*)(out + node * EMBED);
#pragma unroll
    for (int h = 0; h < NHEADS; h++) {
        float o0 = 0.f, o1 = 0.f;
#pragma unroll
        for (int gg = 0; gg < 8; gg++) {
            const float a = sa[w][h * 8 + gg];   // warp-uniform broadcast
            o0 += a * vreg[gg].x;
            o1 += a * vreg[gg].y;
        }
        op2[h * 32 + lane] = __floats2half2_rn(o0, o1);
    }
}

// ---------------- weight + bias conversion, one launch ------------------------
__global__ void __launch_bounds__(256) f2h_all_kernel(
    const float* __restrict__ Wq, const float* __restrict__ Wk,
    const float* __restrict__ Wv, const float* __restrict__ Wo,
    const float* __restrict__ W1, const float* __restrict__ W2,
    const float* __restrict__ bq, const float* __restrict__ bk,
    const float* __restrict__ bv,
    __half* __restrict__ wqkv, __half* __restrict__ wo,
    __half* __restrict__ w1, __half* __restrict__ w2,
    float* __restrict__ bqkv)
{
    int y = blockIdx.y;
    if (y == 6) {
        for (int i = blockIdx.x * blockDim.x + threadIdx.x; i < QKVDIM;
             i += gridDim.x * blockDim.x) {
            float val = (i < EMBED) ? bq[i]
                      : (i < 2 * EMBED) ? bk[i - EMBED] : bv[i - 2 * EMBED];
            bqkv[i] = val;
        }
        return;
    }
    const float* s; __half* d; int n4;
    if      (y == 0) { s = Wq; d = wqkv;                 n4 = EMBED*EMBED/4; }
    else if (y == 1) { s = Wk; d = wqkv + EMBED*EMBED;   n4 = EMBED*EMBED/4; }
    else if (y == 2) { s = Wv; d = wqkv + 2*EMBED*EMBED; n4 = EMBED*EMBED/4; }
    else if (y == 3) { s = Wo; d = wo;                   n4 = EMBED*EMBED/4; }
    else if (y == 4) { s = W1; d = w1;                   n4 = FFDIM*EMBED/4; }
    else             { s = W2; d = w2;                   n4 = FFDIM*EMBED/4; }
    for (int i = blockIdx.x * blockDim.x + threadIdx.x; i < n4; i += gridDim.x * blockDim.x) {
        float4 v = ((const float4*)s)[i];
        __half2* dp = (__half2*)d + i * 2;
        dp[0] = __floats2half2_rn(v.x, v.y);
        dp[1] = __floats2half2_rn(v.z, v.w);
    }
}

// ---------------- host orchestration -----------------------------------------
extern "C" void kernel_launch(void* const* d_in, const int* in_sizes, int n_in,
                              void* d_out, int out_size)
{
    const float* x   = (const float*)d_in[0];
    const float* Wq  = (const float*)d_in[1];
    const float* bq  = (const float*)d_in[2];
    const float* Wk  = (const float*)d_in[3];
    const float* bk  = (const float*)d_in[4];
    const float* Wv  = (const float*)d_in[5];
    const float* bv  = (const float*)d_in[6];
    const float* Wo  = (const float*)d_in[7];
    const float* bo  = (const float*)d_in[8];
    const float* W1  = (const float*)d_in[9];
    const float* b1  = (const float*)d_in[10];
    const float* W2  = (const float*)d_in[11];
    const float* b2  = (const float*)d_in[12];
    const float* g1  = (const float*)d_in[13];
    const float* be1 = (const float*)d_in[14];
    const float* g2  = (const float*)d_in[15];
    const float* be2 = (const float*)d_in[16];
    float* out = (float*)d_out;

    __half *h, *qkv, *attnh, *ffh, *wqkv, *wo, *w1, *w2, *x1h;
    float *bqkv;
    cudaGetSymbolAddress((void**)&h,     g_h);
    cudaGetSymbolAddress((void**)&qkv,   g_qkv);
    cudaGetSymbolAddress((void**)&attnh, g_attnh);
    cudaGetSymbolAddress((void**)&x1h,   g_x1h);
    cudaGetSymbolAddress((void**)&ffh,   g_ffh);
    cudaGetSymbolAddress((void**)&wqkv,  g_wqkv);
    cudaGetSymbolAddress((void**)&wo,    g_wo);
    cudaGetSymbolAddress((void**)&w1,    g_w1);
    cudaGetSymbolAddress((void**)&w2,    g_w2);
    cudaGetSymbolAddress((void**)&bqkv,  g_bqkv);

    cudaFuncSetAttribute(gemm16_kernel<false,false,false,true>,
                         cudaFuncAttributeMaxDynamicSharedMemorySize, GSMEM);
    cudaFuncSetAttribute(gemm16_kernel<false,true,false,true>,
                         cudaFuncAttributeMaxDynamicSharedMemorySize, GSMEM);
    cudaFuncSetAttribute(gemm16_kernel<true,false,false,true>,
                         cudaFuncAttributeMaxDynamicSharedMemorySize, GSMEM);
    cudaFuncSetAttribute(gemm16_kernel<false,true,true,false>,
                         cudaFuncAttributeMaxDynamicSharedMemorySize, GSMEM);

    {
        dim3 g(256, 7);   // y=0..5 weights, y=6 bias concat
        f2h_all_kernel<<<g, 256>>>(Wq, Wk, Wv, Wo, W1, W2, bq, bk, bv,
                                   wqkv, wo, w1, w2, bqkv);
    }

    // 1) h = LN1(x) -> fp16
    ln_kernel<<<N_NODES / 16, 512>>>(x, g1, be1, h);

    // 2) qkv = h @ Wqkv^T + bqkv (fp16 out)
    dim3 grdQKV(QKVDIM / BN, N_NODES / BM);   // (12, 512)
    gemm16_kernel<false,false,false,true><<<grdQKV, 256, GSMEM>>>(h, wqkv, bqkv, nullptr, qkv, EMBED, QKVDIM);

    // 3) per-node attention -> fp16
    attn_kernel<<<N_NODES / 8, 256>>>(qkv, attnh);

    // 4) x1h = x + attnh @ Wo^T + bo (fp16 out, fp32 residual in)
    dim3 grdE(EMBED / BN, N_NODES / BM);      // (4, 512)
    gemm16_kernel<false,true,false,true><<<grdE, 256, GSMEM>>>(attnh, wo, bo, x, x1h, EMBED, EMBED);

    // 5) h = LN2(x1h) -> fp16
    ln_h_kernel<<<N_NODES / 16, 512>>>(x1h, g2, be2, h);

    // 6) ffh = relu(h @ W1^T + b1) -> fp16
    dim3 grdF(FFDIM / BN, N_NODES / BM);      // (16, 512)
    gemm16_kernel<true,false,false,true><<<grdF, 256, GSMEM>>>(h, w1, b1, nullptr, ffh, EMBED, FFDIM);

    // 7) out = x1h + ffh @ W2^T + b2 (fp32 out, fp16 residual in)
    gemm16_kernel<false,true,true,false><<<grdE, 256, GSMEM>>>(ffh, w2, b2, x1h, out, FFDIM, EMBED);
}

// round 16
// speedup vs baseline: 1.2658x; 1.0035x over previous
#include <cuda_runtime.h>
#include <cuda_fp16.h>
#include <math.h>
#include <stdint.h>

#define N_NODES 65536
#define EMBED 512
#define FFDIM 2048
#define QKVDIM 1536
#define NHEADS 8
#define HDIM 64

// ---------------- scratch ----------------------------------------------------
__device__ __half g_h[(size_t)N_NODES * EMBED];
__device__ __half g_qkv[(size_t)N_NODES * QKVDIM];
__device__ __half g_attnh[(size_t)N_NODES * EMBED];
__device__ __half g_x1h[(size_t)N_NODES * EMBED];
__device__ __half g_ffh[(size_t)N_NODES * FFDIM];
__device__ __half g_wqkv[QKVDIM * EMBED];
__device__ float  g_bqkv[QKVDIM];
__device__ __half g_wo[EMBED * EMBED];
__device__ __half g_w1[FFDIM * EMBED];
__device__ __half g_w2[EMBED * FFDIM];

// ---------------- ptx helpers ------------------------------------------------
__device__ __forceinline__ uint32_t smem_u32(const void* p) {
    uint32_t a;
    asm("{ .reg .u64 t; cvta.to.shared.u64 t, %1; cvt.u32.u64 %0, t; }" : "=r"(a) : "l"(p));
    return a;
}
__device__ __forceinline__ void cp_async16(uint32_t saddr, const void* gaddr) {
    asm volatile("cp.async.cg.shared.global [%0], [%1], 16;\n" :: "r"(saddr), "l"(gaddr));
}
__device__ __forceinline__ void cpasync_mbar_arrive(uint32_t mbar) {
    asm volatile("cp.async.mbarrier.arrive.noinc.shared.b64 [%0];" :: "r"(mbar) : "memory");
}
__device__ __forceinline__ void mbar_init(uint32_t mbar, uint32_t cnt) {
    asm volatile("mbarrier.init.shared.b64 [%0], %1;" :: "r"(mbar), "r"(cnt) : "memory");
}
__device__ __forceinline__ void mbar_arrive(uint32_t mbar) {
    asm volatile("mbarrier.arrive.release.cta.shared.b64 _, [%0];" :: "r"(mbar) : "memory");
}
__device__ __forceinline__ void mbar_wait(uint32_t mbar, uint32_t parity) {
    asm volatile(
        "{\n\t.reg .pred P;\n\t"
        "WL%=:\n\t"
        "mbarrier.try_wait.parity.acquire.cta.shared::cta.b64 P, [%0], %1, 0x989680;\n\t"
        "@P bra WD%=;\n\t"
        "bra WL%=;\n\t"
        "WD%=:\n\t}"
        :: "r"(mbar), "r"(parity) : "memory");
}
__device__ __forceinline__ void ldm_x4(uint32_t* r, uint32_t addr) {
    asm volatile("ldmatrix.sync.aligned.m8n8.x4.shared.b16 {%0,%1,%2,%3}, [%4];"
                 : "=r"(r[0]), "=r"(r[1]), "=r"(r[2]), "=r"(r[3]) : "r"(addr));
}
__device__ __forceinline__ void mma16816(float* d, const uint32_t* a, const uint32_t* b) {
    asm volatile(
        "mma.sync.aligned.m16n8k16.row.col.f32.f16.f16.f32 "
        "{%0,%1,%2,%3}, {%4,%5,%6,%7}, {%8,%9}, {%0,%1,%2,%3};"
        : "+f"(d[0]), "+f"(d[1]), "+f"(d[2]), "+f"(d[3])
        : "r"(a[0]), "r"(a[1]), "r"(a[2]), "r"(a[3]), "r"(b[0]), "r"(b[1]));
}

// ---------------- HMMA fp16 GEMM (R8/R11/R14 winner config) -------------------
#define BM 128
#define BN 128
#define BK 64
#define ROWB 144
#define TILEB (128 * ROWB)           // 18432 per tile (A or B)
#define STAGEB (2 * TILEB)           // 36864 per stage
#define GSMEM (64 + 3 * STAGEB)      // 110656

template<bool RELU, bool HASRES, bool RESHALF, bool OUTHALF>
__global__ void __launch_bounds__(256) gemm16_kernel(
    const __half* __restrict__ A, const __half* __restrict__ B,
    const float* __restrict__ bias, const void* __restrict__ resv,
    void* __restrict__ Cv, int K, int M)
{
    extern __shared__ __align__(16) char smem[];
    const uint32_t sb = smem_u32(smem);
    const uint32_t tb = sb + 64;
    const int tid = threadIdx.x;
    const int lane = tid & 31;
    const int wid = tid >> 5;
    const int wm = wid & 3;
    const int wn = wid >> 2;
    const int bm = blockIdx.y * BM;
    const int bn = blockIdx.x * BN;

    if (tid == 0) {
#pragma unroll
        for (int s = 0; s < 3; s++) {
            mbar_init(sb + s * 8, 256);
            mbar_init(sb + 24 + s * 8, 256);
        }
    }
    __syncthreads();

    uint32_t soff[4];
    const __half* agp[4];
    const __half* bgp[4];
#pragma unroll
    for (int i = 0; i < 4; i++) {
        int seg = tid + i * 256;
        int r = seg >> 3, c = seg & 7;
        soff[i] = r * ROWB + c * 16;
        agp[i] = A + (size_t)(bm + r) * K + c * 8;
        bgp[i] = B + (size_t)(bn + r) * K + c * 8;
    }

    uint32_t a_off[2], b_off[4];
#pragma unroll
    for (int mf = 0; mf < 2; mf++)
        a_off[mf] = (wm * 32 + mf * 16 + (lane & 15)) * ROWB + ((lane >> 4) * 16);
#pragma unroll
    for (int p = 0; p < 4; p++)
        b_off[p] = (wn * 64 + p * 16 + ((lane >> 4) << 3) + (lane & 7)) * ROWB
                 + (((lane >> 3) & 1) * 16);

    float acc[2][8][4];
#pragma unroll
    for (int i = 0; i < 2; i++)
#pragma unroll
        for (int j = 0; j < 8; j++)
#pragma unroll
            for (int t = 0; t < 4; t++) acc[i][j][t] = 0.f;

    const int NC = K >> 6;

#pragma unroll
    for (int pc = 0; pc < 2; pc++) {
        const uint32_t base = tb + pc * STAGEB;
        const int ko = pc * BK;
#pragma unroll
        for (int i = 0; i < 4; i++) {
            cp_async16(base + soff[i], agp[i] + ko);
            cp_async16(base + TILEB + soff[i], bgp[i] + ko);
        }
        cpasync_mbar_arrive(sb + pc * 8);
    }

    int st = 0;
    uint32_t pful = 0;
    int pt = 2;
    uint32_t wfree = 1;

#pragma unroll 1
    for (int chunk = 0; chunk < NC; chunk++) {
        const int pc = chunk + 2;
        if (pc < NC) {
            if (pc >= 3) mbar_wait(sb + 24 + pt * 8, wfree);
            const uint32_t base = tb + pt * STAGEB;
            const int ko = pc * BK;
#pragma unroll
            for (int i = 0; i < 4; i++) {
                cp_async16(base + soff[i], agp[i] + ko);
                cp_async16(base + TILEB + soff[i], bgp[i] + ko);
            }
            cpasync_mbar_arrive(sb + pt * 8);
            if (pt == 2) { pt = 0; wfree ^= 1u; } else pt++;
        }

        mbar_wait(sb + st * 8, pful);
        const uint32_t ab = tb + st * STAGEB;
        const uint32_t bb = ab + TILEB;
#pragma unroll
        for (int ks = 0; ks < 4; ks++) {
            uint32_t afr[2][4], bfr[4][4];
            ldm_x4(afr[0], ab + a_off[0] + ks * 32);
            ldm_x4(afr[1], ab + a_off[1] + ks * 32);
#pragma unroll
            for (int p = 0; p < 4; p++) ldm_x4(bfr[p], bb + b_off[p] + ks * 32);
            if (ks == 3) mbar_arrive(sb + 24 + st * 8);
#pragma unroll
            for (int mf = 0; mf < 2; mf++)
#pragma unroll
                for (int nf = 0; nf < 8; nf++)
                    mma16816(acc[mf][nf], afr[mf], &bfr[nf >> 1][(nf & 1) * 2]);
        }
        if (st == 2) { st = 0; pful ^= 1u; } else st++;
    }

    const int mrow = bm + wm * 32 + (lane >> 2);
    const int ncol = bn + wn * 64 + (lane & 3) * 2;
#pragma unroll
    for (int mf = 0; mf < 2; mf++) {
#pragma unroll
        for (int half8 = 0; half8 < 2; half8++) {
            const int row = mrow + mf * 16 + half8 * 8;
#pragma unroll
            for (int nf = 0; nf < 8; nf++) {
                const int col = ncol + nf * 8;
                float c0 = acc[mf][nf][half8 * 2 + 0];
                float c1 = acc[mf][nf][half8 * 2 + 1];
                float2 b2 = *(const float2*)&bias[col];
                c0 += b2.x; c1 += b2.y;
                if (RELU) { c0 = fmaxf(c0, 0.f); c1 = fmaxf(c1, 0.f); }
                if (HASRES) {
                    if (RESHALF) {
                        __half2 r2 = *(const __half2*)((const __half*)resv + (size_t)row * M + col);
                        float2 rf = __half22float2(r2);
                        c0 += rf.x; c1 += rf.y;
                    } else {
                        float2 r2 = *(const float2*)((const float*)resv + (size_t)row * M + col);
                        c0 += r2.x; c1 += r2.y;
                    }
                }
                if (OUTHALF) {
                    *(__half2*)((__half*)Cv + (size_t)row * M + col) =
                        __floats2half2_rn(c0, c1);
                } else {
                    *(float2*)((float*)Cv + (size_t)row * M + col) =
                        make_float2(c0, c1);
                }
            }
        }
    }
}

// ---------------- LayerNorm (fp32 in) -> fp16, warp-per-row, 16 rows/blk -----
__global__ void __launch_bounds__(512) ln_kernel(
    const float* __restrict__ x, const float* __restrict__ gamma,
    const float* __restrict__ beta, __half* __restrict__ y)
{
    const int w = threadIdx.x >> 5, lane = threadIdx.x & 31;
    const size_t row = (size_t)blockIdx.x * 16 + w;
    const float4* xp = (const float4*)(x + row * EMBED);
    float4 v[4];
    float s = 0.f, s2 = 0.f;
#pragma unroll
    for (int k = 0; k < 4; k++) {
        v[k] = xp[k * 32 + lane];
        s  += v[k].x + v[k].y + v[k].z + v[k].w;
        s2 += v[k].x*v[k].x + v[k].y*v[k].y + v[k].z*v[k].z + v[k].w*v[k].w;
    }
#pragma unroll
    for (int o = 16; o > 0; o >>= 1) {
        s  += __shfl_xor_sync(0xffffffffu, s,  o);
        s2 += __shfl_xor_sync(0xffffffffu, s2, o);
    }
    const float mu = s * (1.0f / EMBED);
    const float inv = rsqrtf(s2 * (1.0f / EMBED) - mu * mu + 1e-5f);
    __half2* yp = (__half2*)(y + row * EMBED);
#pragma unroll
    for (int k = 0; k < 4; k++) {
        float4 g4 = ((const float4*)gamma)[k * 32 + lane];
        float4 b4 = ((const float4*)beta)[k * 32 + lane];
        yp[(k * 32 + lane) * 2] =
            __floats2half2_rn((v[k].x - mu) * inv * g4.x + b4.x,
                              (v[k].y - mu) * inv * g4.y + b4.y);
        yp[(k * 32 + lane) * 2 + 1] =
            __floats2half2_rn((v[k].z - mu) * inv * g4.z + b4.z,
                              (v[k].w - mu) * inv * g4.w + b4.w);
    }
}

// ---------------- LayerNorm (fp16 in) -> fp16, warp-per-row, 16 rows/blk -----
__global__ void __launch_bounds__(512) ln_h_kernel(
    const __half* __restrict__ x, const float* __restrict__ gamma,
    const float* __restrict__ beta, __half* __restrict__ y)
{
    const int w = threadIdx.x >> 5, lane = threadIdx.x & 31;
    const size_t row = (size_t)blockIdx.x * 16 + w;
    const uint4* xp = (const uint4*)(x + row * EMBED);
    uint4 raw[2];
    float f[16];
    float s = 0.f, s2 = 0.f;
#pragma unroll
    for (int k = 0; k < 2; k++) {
        raw[k] = xp[k * 32 + lane];
        const __half2* hp = (const __half2*)&raw[k];
#pragma unroll
        for (int j = 0; j < 4; j++) {
            float2 fj = __half22float2(hp[j]);
            f[k * 8 + j * 2]     = fj.x;
            f[k * 8 + j * 2 + 1] = fj.y;
            s  += fj.x + fj.y;
            s2 += fj.x * fj.x + fj.y * fj.y;
        }
    }
#pragma unroll
    for (int o = 16; o > 0; o >>= 1) {
        s  += __shfl_xor_sync(0xffffffffu, s,  o);
        s2 += __shfl_xor_sync(0xffffffffu, s2, o);
    }
    const float mu = s * (1.0f / EMBED);
    const float inv = rsqrtf(s2 * (1.0f / EMBED) - mu * mu + 1e-5f);
    __half2* yp = (__half2*)(y + row * EMBED);
#pragma unroll
    for (int k = 0; k < 2; k++) {
        const int base4 = (k * 32 + lane) * 2;
#pragma unroll
        for (int q = 0; q < 2; q++) {
            float4 g4 = ((const float4*)gamma)[base4 + q];
            float4 b4 = ((const float4*)beta)[base4 + q];
            yp[(base4 + q) * 2] =
                __floats2half2_rn((f[k*8 + q*4 + 0] - mu) * inv * g4.x + b4.x,
                                  (f[k*8 + q*4 + 1] - mu) * inv * g4.y + b4.y);
            yp[(base4 + q) * 2 + 1] =
                __floats2half2_rn((f[k*8 + q*4 + 2] - mu) * inv * g4.z + b4.z,
                                  (f[k*8 + q*4 + 3] - mu) * inv * g4.w + b4.w);
        }
    }
}

// ---------------- per-node attention, warp-per-node ---------------------------
// q,k staged in SMEM (vectorized, rotated LDS.128); V loaded DIRECTLY from
// global into registers (coalesced 128B per g, issued before the score phase
// to overlap latency). SMEM footprint 27KB -> 18.5KB; removes V's SMEM
// store+load round trip entirely.
__device__ __forceinline__ float dot8(uint4 a, uint4 b) {
    const __half2* ah = (const __half2*)&a;
    const __half2* bh = (const __half2*)&b;
    float r = 0.f;
#pragma unroll
    for (int j = 0; j < 4; j++) {
        float2 af = __half22float2(ah[j]);
        float2 bf = __half22float2(bh[j]);
        r += af.x * bf.x + af.y * bf.y;
    }
    return r;
}

__global__ void __launch_bounds__(256) attn_kernel(
    const __half* __restrict__ qkv, __half* __restrict__ out)
{
    const int w = threadIdx.x >> 5, lane = threadIdx.x & 31;
    const size_t node = (size_t)blockIdx.x * 8 + w;

    __shared__ __half s[8][2 * EMBED];   // q|k only: 16 KB
    __shared__ float sa[8][64];          // 2 KB

    // start V loads global->register early (independent of q/k staging)
    const __half2* gv2 = (const __half2*)(qkv + node * QKVDIM + 2 * EMBED);
    __half2 vh[8];
#pragma unroll
    for (int gg = 0; gg < 8; gg++) vh[gg] = gv2[gg * 32 + lane];

    // stage q|k: 1024 halfs = 128 uint4, 4 per lane
    const uint4* rp = (const uint4*)(qkv + node * QKVDIM);
    uint4* sp = (uint4*)s[w];
#pragma unroll
    for (int i = 0; i < 4; i++) sp[i * 32 + lane] = rp[i * 32 + lane];
    __syncwarp();

    const uint4* q4 = (const uint4*)(s[w]);            // q rows: 8 uint4 each
    const uint4* k4 = (const uint4*)(s[w] + EMBED);    // k rows

    // scores: lane covers pairs (h0, g) and (h0+4, g); h0 = lane>>3, g = lane&7
    const int h0 = lane >> 3, g = lane & 7;
    float a0 = 0.f, a1 = 0.f;
#pragma unroll
    for (int o = 0; o < 8; o++) {
        const int j = (o + g) & 7;
        uint4 kv = k4[g * 8 + j];
        uint4 q0 = q4[h0 * 8 + j];
        uint4 q1 = q4[(h0 + 4) * 8 + j];
        a0 += dot8(q0, kv);
        a1 += dot8(q1, kv);
    }
    float sc[2] = { a0 * 0.125f, a1 * 0.125f };

    // softmax over 8-lane groups
#pragma unroll
    for (int pi = 0; pi < 2; pi++) {
        float m = sc[pi];
#pragma unroll
        for (int o = 4; o > 0; o >>= 1)
            m = fmaxf(m, __shfl_xor_sync(0xffffffffu, m, o));
        float e = expf(sc[pi] - m);
        float ssum = e;
#pragma unroll
        for (int o = 4; o > 0; o >>= 1)
            ssum += __shfl_xor_sync(0xffffffffu, ssum, o);
        sa[w][lane + pi * 32] = e / ssum;
    }
    __syncwarp();

    // convert V registers and accumulate output
    float2 vreg[8];
#pragma unroll
    for (int gg = 0; gg < 8; gg++) vreg[gg] = __half22float2(vh[gg]);

    __half2* op2 = (__half2*)(out + node * EMBED);
#pragma unroll
    for (int h = 0; h < NHEADS; h++) {
        float o0 = 0.f, o1 = 0.f;
#pragma unroll
        for (int gg = 0; gg < 8; gg++) {
            const float a = sa[w][h * 8 + gg];   // warp-uniform broadcast
            o0 += a * vreg[gg].x;
            o1 += a * vreg[gg].y;
        }
        op2[h * 32 + lane] = __floats2half2_rn(o0, o1);
    }
}

// ---------------- weight + bias conversion, one launch ------------------------
__global__ void __launch_bounds__(256) f2h_all_kernel(
    const float* __restrict__ Wq, const float* __restrict__ Wk,
    const float* __restrict__ Wv, const float* __restrict__ Wo,
    const float* __restrict__ W1, const float* __restrict__ W2,
    const float* __restrict__ bq, const float* __restrict__ bk,
    const float* __restrict__ bv,
    __half* __restrict__ wqkv, __half* __restrict__ wo,
    __half* __restrict__ w1, __half* __restrict__ w2,
    float* __restrict__ bqkv)
{
    int y = blockIdx.y;
    if (y == 6) {
        for (int i = blockIdx.x * blockDim.x + threadIdx.x; i < QKVDIM;
             i += gridDim.x * blockDim.x) {
            float val = (i < EMBED) ? bq[i]
                      : (i < 2 * EMBED) ? bk[i - EMBED] : bv[i - 2 * EMBED];
            bqkv[i] = val;
        }
        return;
    }
    const float* s; __half* d; int n4;
    if      (y == 0) { s = Wq; d = wqkv;                 n4 = EMBED*EMBED/4; }
    else if (y == 1) { s = Wk; d = wqkv + EMBED*EMBED;   n4 = EMBED*EMBED/4; }
    else if (y == 2) { s = Wv; d = wqkv + 2*EMBED*EMBED; n4 = EMBED*EMBED/4; }
    else if (y == 3) { s = Wo; d = wo;                   n4 = EMBED*EMBED/4; }
    else if (y == 4) { s = W1; d = w1;                   n4 = FFDIM*EMBED/4; }
    else             { s = W2; d = w2;                   n4 = FFDIM*EMBED/4; }
    for (int i = blockIdx.x * blockDim.x + threadIdx.x; i < n4; i += gridDim.x * blockDim.x) {
        float4 v = ((const float4*)s)[i];
        __half2* dp = (__half2*)d + i * 2;
        dp[0] = __floats2half2_rn(v.x, v.y);
        dp[1] = __floats2half2_rn(v.z, v.w);
    }
}

// ---------------- host orchestration -----------------------------------------
extern "C" void kernel_launch(void* const* d_in, const int* in_sizes, int n_in,
                              void* d_out, int out_size)
{
    const float* x   = (const float*)d_in[0];
    const float* Wq  = (const float*)d_in[1];
    const float* bq  = (const float*)d_in[2];
    const float* Wk  = (const float*)d_in[3];
    const float* bk  = (const float*)d_in[4];
    const float* Wv  = (const float*)d_in[5];
    const float* bv  = (const float*)d_in[6];
    const float* Wo  = (const float*)d_in[7];
    const float* bo  = (const float*)d_in[8];
    const float* W1  = (const float*)d_in[9];
    const float* b1  = (const float*)d_in[10];
    const float* W2  = (const float*)d_in[11];
    const float* b2  = (const float*)d_in[12];
    const float* g1  = (const float*)d_in[13];
    const float* be1 = (const float*)d_in[14];
    const float* g2  = (const float*)d_in[15];
    const float* be2 = (const float*)d_in[16];
    float* out = (float*)d_out;

    __half *h, *qkv, *attnh, *ffh, *wqkv, *wo, *w1, *w2, *x1h;
    float *bqkv;
    cudaGetSymbolAddress((void**)&h,     g_h);
    cudaGetSymbolAddress((void**)&qkv,   g_qkv);
    cudaGetSymbolAddress((void**)&attnh, g_attnh);
    cudaGetSymbolAddress((void**)&x1h,   g_x1h);
    cudaGetSymbolAddress((void**)&ffh,   g_ffh);
    cudaGetSymbolAddress((void**)&wqkv,  g_wqkv);
    cudaGetSymbolAddress((void**)&wo,    g_wo);
    cudaGetSymbolAddress((void**)&w1,    g_w1);
    cudaGetSymbolAddress((void**)&w2,    g_w2);
    cudaGetSymbolAddress((void**)&bqkv,  g_bqkv);

    cudaFuncSetAttribute(gemm16_kernel<false,false,false,true>,
                         cudaFuncAttributeMaxDynamicSharedMemorySize, GSMEM);
    cudaFuncSetAttribute(gemm16_kernel<false,true,false,true>,
                         cudaFuncAttributeMaxDynamicSharedMemorySize, GSMEM);
    cudaFuncSetAttribute(gemm16_kernel<true,false,false,true>,
                         cudaFuncAttributeMaxDynamicSharedMemorySize, GSMEM);
    cudaFuncSetAttribute(gemm16_kernel<false,true,true,false>,
                         cudaFuncAttributeMaxDynamicSharedMemorySize, GSMEM);

    {
        dim3 g(256, 7);   // y=0..5 weights, y=6 bias concat
        f2h_all_kernel<<<g, 256>>>(Wq, Wk, Wv, Wo, W1, W2, bq, bk, bv,
                                   wqkv, wo, w1, w2, bqkv);
    }

    // 1) h = LN1(x) -> fp16
    ln_kernel<<<N_NODES / 16, 512>>>(x, g1, be1, h);

    // 2) qkv = h @ Wqkv^T + bqkv (fp16 out)
    dim3 grdQKV(QKVDIM / BN, N_NODES / BM);   // (12, 512)
    gemm16_kernel<false,false,false,true><<<grdQKV, 256, GSMEM>>>(h, wqkv, bqkv, nullptr, qkv, EMBED, QKVDIM);

    // 3) per-node attention -> fp16
    attn_kernel<<<N_NODES / 8, 256>>>(qkv, attnh);

    // 4) x1h = x + attnh @ Wo^T + bo (fp16 out, fp32 residual in)
    dim3 grdE(EMBED / BN, N_NODES / BM);      // (4, 512)
    gemm16_kernel<false,true,false,true><<<grdE, 256, GSMEM>>>(attnh, wo, bo, x, x1h, EMBED, EMBED);

    // 5) h = LN2(x1h) -> fp16
    ln_h_kernel<<<N_NODES / 16, 512>>>(x1h, g2, be2, h);

    // 6) ffh = relu(h @ W1^T + b1) -> fp16
    dim3 grdF(FFDIM / BN, N_NODES / BM);      // (16, 512)
    gemm16_kernel<true,false,false,true><<<grdF, 256, GSMEM>>>(h, w1, b1, nullptr, ffh, EMBED, FFDIM);

    // 7) out = x1h + ffh @ W2^T + b2 (fp32 out, fp16 residual in)
    gemm16_kernel<false,true,true,false><<<grdE, 256, GSMEM>>>(ffh, w2, b2, x1h, out, FFDIM, EMBED);
}

// round 17
// speedup vs baseline: 1.2752x; 1.0074x over previous
#include <cuda_runtime.h>
#include <cuda_fp16.h>
#include <math.h>
#include <stdint.h>

#define N_NODES 65536
#define EMBED 512
#define FFDIM 2048
#define QKVDIM 1536
#define NHEADS 8
#define HDIM 64

// ---------------- scratch ----------------------------------------------------
__device__ __half g_h[(size_t)N_NODES * EMBED];
__device__ __half g_qkv[(size_t)N_NODES * QKVDIM];
__device__ __half g_attnh[(size_t)N_NODES * EMBED];
__device__ __half g_x1h[(size_t)N_NODES * EMBED];
__device__ __half g_ffh[(size_t)N_NODES * FFDIM];
__device__ __half g_wqkv[QKVDIM * EMBED];
__device__ float  g_bqkv[QKVDIM];
__device__ __half g_wo[EMBED * EMBED];
__device__ __half g_w1[FFDIM * EMBED];
__device__ __half g_w2[EMBED * FFDIM];

// ---------------- ptx helpers ------------------------------------------------
__device__ __forceinline__ uint32_t smem_u32(const void* p) {
    uint32_t a;
    asm("{ .reg .u64 t; cvta.to.shared.u64 t, %1; cvt.u32.u64 %0, t; }" : "=r"(a) : "l"(p));
    return a;
}
__device__ __forceinline__ void cp_async16(uint32_t saddr, const void* gaddr) {
    asm volatile("cp.async.cg.shared.global [%0], [%1], 16;\n" :: "r"(saddr), "l"(gaddr));
}
__device__ __forceinline__ void cpasync_mbar_arrive(uint32_t mbar) {
    asm volatile("cp.async.mbarrier.arrive.noinc.shared.b64 [%0];" :: "r"(mbar) : "memory");
}
__device__ __forceinline__ void mbar_init(uint32_t mbar, uint32_t cnt) {
    asm volatile("mbarrier.init.shared.b64 [%0], %1;" :: "r"(mbar), "r"(cnt) : "memory");
}
__device__ __forceinline__ void mbar_arrive(uint32_t mbar) {
    asm volatile("mbarrier.arrive.release.cta.shared.b64 _, [%0];" :: "r"(mbar) : "memory");
}
__device__ __forceinline__ void mbar_wait(uint32_t mbar, uint32_t parity) {
    asm volatile(
        "{\n\t.reg .pred P;\n\t"
        "WL%=:\n\t"
        "mbarrier.try_wait.parity.acquire.cta.shared::cta.b64 P, [%0], %1, 0x989680;\n\t"
        "@P bra WD%=;\n\t"
        "bra WL%=;\n\t"
        "WD%=:\n\t}"
        :: "r"(mbar), "r"(parity) : "memory");
}
__device__ __forceinline__ void ldm_x4(uint32_t* r, uint32_t addr) {
    asm volatile("ldmatrix.sync.aligned.m8n8.x4.shared.b16 {%0,%1,%2,%3}, [%4];"
                 : "=r"(r[0]), "=r"(r[1]), "=r"(r[2]), "=r"(r[3]) : "r"(addr));
}
__device__ __forceinline__ void mma16816(float* d, const uint32_t* a, const uint32_t* b) {
    asm volatile(
        "mma.sync.aligned.m16n8k16.row.col.f32.f16.f16.f32 "
        "{%0,%1,%2,%3}, {%4,%5,%6,%7}, {%8,%9}, {%0,%1,%2,%3};"
        : "+f"(d[0]), "+f"(d[1]), "+f"(d[2]), "+f"(d[3])
        : "r"(a[0]), "r"(a[1]), "r"(a[2]), "r"(a[3]), "r"(b[0]), "r"(b[1]));
}

// ---------------- HMMA fp16 GEMM (R8/R11/R14 winner config) -------------------
#define BM 128
#define BN 128
#define BK 64
#define ROWB 144
#define TILEB (128 * ROWB)           // 18432 per tile (A or B)
#define STAGEB (2 * TILEB)           // 36864 per stage
#define GSMEM (64 + 3 * STAGEB)      // 110656

template<bool RELU, bool HASRES, bool RESHALF, bool OUTHALF>
__global__ void __launch_bounds__(256) gemm16_kernel(
    const __half* __restrict__ A, const __half* __restrict__ B,
    const float* __restrict__ bias, const void* __restrict__ resv,
    void* __restrict__ Cv, int K, int M)
{
    extern __shared__ __align__(16) char smem[];
    const uint32_t sb = smem_u32(smem);
    const uint32_t tb = sb + 64;
    const int tid = threadIdx.x;
    const int lane = tid & 31;
    const int wid = tid >> 5;
    const int wm = wid & 3;
    const int wn = wid >> 2;
    const int bm = blockIdx.y * BM;
    const int bn = blockIdx.x * BN;

    if (tid == 0) {
#pragma unroll
        for (int s = 0; s < 3; s++) {
            mbar_init(sb + s * 8, 256);
            mbar_init(sb + 24 + s * 8, 256);
        }
    }
    __syncthreads();

    uint32_t soff[4];
    const __half* agp[4];
    const __half* bgp[4];
#pragma unroll
    for (int i = 0; i < 4; i++) {
        int seg = tid + i * 256;
        int r = seg >> 3, c = seg & 7;
        soff[i] = r * ROWB + c * 16;
        agp[i] = A + (size_t)(bm + r) * K + c * 8;
        bgp[i] = B + (size_t)(bn + r) * K + c * 8;
    }

    uint32_t a_off[2], b_off[4];
#pragma unroll
    for (int mf = 0; mf < 2; mf++)
        a_off[mf] = (wm * 32 + mf * 16 + (lane & 15)) * ROWB + ((lane >> 4) * 16);
#pragma unroll
    for (int p = 0; p < 4; p++)
        b_off[p] = (wn * 64 + p * 16 + ((lane >> 4) << 3) + (lane & 7)) * ROWB
                 + (((lane >> 3) & 1) * 16);

    float acc[2][8][4];
#pragma unroll
    for (int i = 0; i < 2; i++)
#pragma unroll
        for (int j = 0; j < 8; j++)
#pragma unroll
            for (int t = 0; t < 4; t++) acc[i][j][t] = 0.f;

    const int NC = K >> 6;

#pragma unroll
    for (int pc = 0; pc < 2; pc++) {
        const uint32_t base = tb + pc * STAGEB;
        const int ko = pc * BK;
#pragma unroll
        for (int i = 0; i < 4; i++) {
            cp_async16(base + soff[i], agp[i] + ko);
            cp_async16(base + TILEB + soff[i], bgp[i] + ko);
        }
        cpasync_mbar_arrive(sb + pc * 8);
    }

    int st = 0;
    uint32_t pful = 0;
    int pt = 2;
    uint32_t wfree = 1;

#pragma unroll 1
    for (int chunk = 0; chunk < NC; chunk++) {
        const int pc = chunk + 2;
        if (pc < NC) {
            if (pc >= 3) mbar_wait(sb + 24 + pt * 8, wfree);
            const uint32_t base = tb + pt * STAGEB;
            const int ko = pc * BK;
#pragma unroll
            for (int i = 0; i < 4; i++) {
                cp_async16(base + soff[i], agp[i] + ko);
                cp_async16(base + TILEB + soff[i], bgp[i] + ko);
            }
            cpasync_mbar_arrive(sb + pt * 8);
            if (pt == 2) { pt = 0; wfree ^= 1u; } else pt++;
        }

        mbar_wait(sb + st * 8, pful);
        const uint32_t ab = tb + st * STAGEB;
        const uint32_t bb = ab + TILEB;
#pragma unroll
        for (int ks = 0; ks < 4; ks++) {
            uint32_t afr[2][4], bfr[4][4];
            ldm_x4(afr[0], ab + a_off[0] + ks * 32);
            ldm_x4(afr[1], ab + a_off[1] + ks * 32);
#pragma unroll
            for (int p = 0; p < 4; p++) ldm_x4(bfr[p], bb + b_off[p] + ks * 32);
            if (ks == 3) mbar_arrive(sb + 24 + st * 8);
#pragma unroll
            for (int mf = 0; mf < 2; mf++)
#pragma unroll
                for (int nf = 0; nf < 8; nf++)
                    mma16816(acc[mf][nf], afr[mf], &bfr[nf >> 1][(nf & 1) * 2]);
        }
        if (st == 2) { st = 0; pful ^= 1u; } else st++;
    }

    const int mrow = bm + wm * 32 + (lane >> 2);
    const int ncol = bn + wn * 64 + (lane & 3) * 2;
#pragma unroll
    for (int mf = 0; mf < 2; mf++) {
#pragma unroll
        for (int half8 = 0; half8 < 2; half8++) {
            const int row = mrow + mf * 16 + half8 * 8;
#pragma unroll
            for (int nf = 0; nf < 8; nf++) {
                const int col = ncol + nf * 8;
                float c0 = acc[mf][nf][half8 * 2 + 0];
                float c1 = acc[mf][nf][half8 * 2 + 1];
                float2 b2 = *(const float2*)&bias[col];
                c0 += b2.x; c1 += b2.y;
                if (RELU) { c0 = fmaxf(c0, 0.f); c1 = fmaxf(c1, 0.f); }
                if (HASRES) {
                    if (RESHALF) {
                        __half2 r2 = *(const __half2*)((const __half*)resv + (size_t)row * M + col);
                        float2 rf = __half22float2(r2);
                        c0 += rf.x; c1 += rf.y;
                    } else {
                        float2 r2 = *(const float2*)((const float*)resv + (size_t)row * M + col);
                        c0 += r2.x; c1 += r2.y;
                    }
                }
                if (OUTHALF) {
                    *(__half2*)((__half*)Cv + (size_t)row * M + col) =
                        __floats2half2_rn(c0, c1);
                } else {
                    *(float2*)((float*)Cv + (size_t)row * M + col) =
                        make_float2(c0, c1);
                }
            }
        }
    }
}

// ---------------- LayerNorm (fp32 in) -> fp16, warp-per-row, 16 rows/blk -----
__global__ void __launch_bounds__(512) ln_kernel(
    const float* __restrict__ x, const float* __restrict__ gamma,
    const float* __restrict__ beta, __half* __restrict__ y)
{
    const int w = threadIdx.x >> 5, lane = threadIdx.x & 31;
    const size_t row = (size_t)blockIdx.x * 16 + w;
    const float4* xp = (const float4*)(x + row * EMBED);
    float4 v[4];
    float s = 0.f, s2 = 0.f;
#pragma unroll
    for (int k = 0; k < 4; k++) {
        v[k] = xp[k * 32 + lane];
        s  += v[k].x + v[k].y + v[k].z + v[k].w;
        s2 += v[k].x*v[k].x + v[k].y*v[k].y + v[k].z*v[k].z + v[k].w*v[k].w;
    }
#pragma unroll
    for (int o = 16; o > 0; o >>= 1) {
        s  += __shfl_xor_sync(0xffffffffu, s,  o);
        s2 += __shfl_xor_sync(0xffffffffu, s2, o);
    }
    const float mu = s * (1.0f / EMBED);
    const float inv = rsqrtf(s2 * (1.0f / EMBED) - mu * mu + 1e-5f);
    __half2* yp = (__half2*)(y + row * EMBED);
#pragma unroll
    for (int k = 0; k < 4; k++) {
        float4 g4 = ((const float4*)gamma)[k * 32 + lane];
        float4 b4 = ((const float4*)beta)[k * 32 + lane];
        yp[(k * 32 + lane) * 2] =
            __floats2half2_rn((v[k].x - mu) * inv * g4.x + b4.x,
                              (v[k].y - mu) * inv * g4.y + b4.y);
        yp[(k * 32 + lane) * 2 + 1] =
            __floats2half2_rn((v[k].z - mu) * inv * g4.z + b4.z,
                              (v[k].w - mu) * inv * g4.w + b4.w);
    }
}

// ---------------- LayerNorm (fp16 in) -> fp16, warp-per-row, 16 rows/blk -----
__global__ void __launch_bounds__(512) ln_h_kernel(
    const __half* __restrict__ x, const float* __restrict__ gamma,
    const float* __restrict__ beta, __half* __restrict__ y)
{
    const int w = threadIdx.x >> 5, lane = threadIdx.x & 31;
    const size_t row = (size_t)blockIdx.x * 16 + w;
    const uint4* xp = (const uint4*)(x + row * EMBED);
    uint4 raw[2];
    float f[16];
    float s = 0.f, s2 = 0.f;
#pragma unroll
    for (int k = 0; k < 2; k++) {
        raw[k] = xp[k * 32 + lane];
        const __half2* hp = (const __half2*)&raw[k];
#pragma unroll
        for (int j = 0; j < 4; j++) {
            float2 fj = __half22float2(hp[j]);
            f[k * 8 + j * 2]     = fj.x;
            f[k * 8 + j * 2 + 1] = fj.y;
            s  += fj.x + fj.y;
            s2 += fj.x * fj.x + fj.y * fj.y;
        }
    }
#pragma unroll
    for (int o = 16; o > 0; o >>= 1) {
        s  += __shfl_xor_sync(0xffffffffu, s,  o);
        s2 += __shfl_xor_sync(0xffffffffu, s2, o);
    }
    const float mu = s * (1.0f / EMBED);
    const float inv = rsqrtf(s2 * (1.0f / EMBED) - mu * mu + 1e-5f);
    __half2* yp = (__half2*)(y + row * EMBED);
#pragma unroll
    for (int k = 0; k < 2; k++) {
        const int base4 = (k * 32 + lane) * 2;
#pragma unroll
        for (int q = 0; q < 2; q++) {
            float4 g4 = ((const float4*)gamma)[base4 + q];
            float4 b4 = ((const float4*)beta)[base4 + q];
            yp[(base4 + q) * 2] =
                __floats2half2_rn((f[k*8 + q*4 + 0] - mu) * inv * g4.x + b4.x,
                                  (f[k*8 + q*4 + 1] - mu) * inv * g4.y + b4.y);
            yp[(base4 + q) * 2 + 1] =
                __floats2half2_rn((f[k*8 + q*4 + 2] - mu) * inv * g4.z + b4.z,
                                  (f[k*8 + q*4 + 3] - mu) * inv * g4.w + b4.w);
        }
    }
}

// ---------------- per-node attention, warp-per-node ---------------------------
// q,k staged in SMEM (vectorized, rotated LDS.128); V loaded directly from
// global into registers. Score octet dot products use HFMA2 pair-math (fp16
// accumulation confined to 8-element octets; cross-octet sums stay fp32).
__device__ __forceinline__ float dot8h(uint4 a, uint4 b) {
    const __half2* ah = (const __half2*)&a;
    const __half2* bh = (const __half2*)&b;
    __half2 acc = __hmul2(ah[0], bh[0]);
    acc = __hfma2(ah[1], bh[1], acc);
    acc = __hfma2(ah[2], bh[2], acc);
    acc = __hfma2(ah[3], bh[3], acc);
    float2 f = __half22float2(acc);
    return f.x + f.y;
}

__global__ void __launch_bounds__(256) attn_kernel(
    const __half* __restrict__ qkv, __half* __restrict__ out)
{
    const int w = threadIdx.x >> 5, lane = threadIdx.x & 31;
    const size_t node = (size_t)blockIdx.x * 8 + w;

    __shared__ __half s[8][2 * EMBED];   // q|k only: 16 KB
    __shared__ float sa[8][64];          // 2 KB

    // start V loads global->register early
    const __half2* gv2 = (const __half2*)(qkv + node * QKVDIM + 2 * EMBED);
    __half2 vh[8];
#pragma unroll
    for (int gg = 0; gg < 8; gg++) vh[gg] = gv2[gg * 32 + lane];

    // stage q|k: 128 uint4, 4 per lane
    const uint4* rp = (const uint4*)(qkv + node * QKVDIM);
    uint4* sp = (uint4*)s[w];
#pragma unroll
    for (int i = 0; i < 4; i++) sp[i * 32 + lane] = rp[i * 32 + lane];
    __syncwarp();

    const uint4* q4 = (const uint4*)(s[w]);
    const uint4* k4 = (const uint4*)(s[w] + EMBED);

    const int h0 = lane >> 3, g = lane & 7;
    float a0 = 0.f, a1 = 0.f;
#pragma unroll
    for (int o = 0; o < 8; o++) {
        const int j = (o + g) & 7;
        uint4 kv = k4[g * 8 + j];
        uint4 q0 = q4[h0 * 8 + j];
        uint4 q1 = q4[(h0 + 4) * 8 + j];
        a0 += dot8h(q0, kv);
        a1 += dot8h(q1, kv);
    }
    float sc[2] = { a0 * 0.125f, a1 * 0.125f };

    // softmax over 8-lane groups
#pragma unroll
    for (int pi = 0; pi < 2; pi++) {
        float m = sc[pi];
#pragma unroll
        for (int o = 4; o > 0; o >>= 1)
            m = fmaxf(m, __shfl_xor_sync(0xffffffffu, m, o));
        float e = expf(sc[pi] - m);
        float ssum = e;
#pragma unroll
        for (int o = 4; o > 0; o >>= 1)
            ssum += __shfl_xor_sync(0xffffffffu, ssum, o);
        sa[w][lane + pi * 32] = e / ssum;
    }
    __syncwarp();

    float2 vreg[8];
#pragma unroll
    for (int gg = 0; gg < 8; gg++) vreg[gg] = __half22float2(vh[gg]);

    __half2* op2 = (__half2*)(out + node * EMBED);
#pragma unroll
    for (int h = 0; h < NHEADS; h++) {
        float o0 = 0.f, o1 = 0.f;
#pragma unroll
        for (int gg = 0; gg < 8; gg++) {
            const float a = sa[w][h * 8 + gg];
            o0 += a * vreg[gg].x;
            o1 += a * vreg[gg].y;
        }
        op2[h * 32 + lane] = __floats2half2_rn(o0, o1);
    }
}

// ---------------- weight + bias conversion, one launch ------------------------
__global__ void __launch_bounds__(256) f2h_all_kernel(
    const float* __restrict__ Wq, const float* __restrict__ Wk,
    const float* __restrict__ Wv, const float* __restrict__ Wo,
    const float* __restrict__ W1, const float* __restrict__ W2,
    const float* __restrict__ bq, const float* __restrict__ bk,
    const float* __restrict__ bv,
    __half* __restrict__ wqkv, __half* __restrict__ wo,
    __half* __restrict__ w1, __half* __restrict__ w2,
    float* __restrict__ bqkv)
{
    int y = blockIdx.y;
    if (y == 6) {
        for (int i = blockIdx.x * blockDim.x + threadIdx.x; i < QKVDIM;
             i += gridDim.x * blockDim.x) {
            float val = (i < EMBED) ? bq[i]
                      : (i < 2 * EMBED) ? bk[i - EMBED] : bv[i - 2 * EMBED];
            bqkv[i] = val;
        }
        return;
    }
    const float* s; __half* d; int n4;
    if      (y == 0) { s = Wq; d = wqkv;                 n4 = EMBED*EMBED/4; }
    else if (y == 1) { s = Wk; d = wqkv + EMBED*EMBED;   n4 = EMBED*EMBED/4; }
    else if (y == 2) { s = Wv; d = wqkv + 2*EMBED*EMBED; n4 = EMBED*EMBED/4; }
    else if (y == 3) { s = Wo; d = wo;                   n4 = EMBED*EMBED/4; }
    else if (y == 4) { s = W1; d = w1;                   n4 = FFDIM*EMBED/4; }
    else             { s = W2; d = w2;                   n4 = FFDIM*EMBED/4; }
    for (int i = blockIdx.x * blockDim.x + threadIdx.x; i < n4; i += gridDim.x * blockDim.x) {
        float4 v = ((const float4*)s)[i];
        __half2* dp = (__half2*)d + i * 2;
        dp[0] = __floats2half2_rn(v.x, v.y);
        dp[1] = __floats2half2_rn(v.z, v.w);
    }
}

// ---------------- host orchestration -----------------------------------------
extern "C" void kernel_launch(void* const* d_in, const int* in_sizes, int n_in,
                              void* d_out, int out_size)
{
    const float* x   = (const float*)d_in[0];
    const float* Wq  = (const float*)d_in[1];
    const float* bq  = (const float*)d_in[2];
    const float* Wk  = (const float*)d_in[3];
    const float* bk  = (const float*)d_in[4];
    const float* Wv  = (const float*)d_in[5];
    const float* bv  = (const float*)d_in[6];
    const float* Wo  = (const float*)d_in[7];
    const float* bo  = (const float*)d_in[8];
    const float* W1  = (const float*)d_in[9];
    const float* b1  = (const float*)d_in[10];
    const float* W2  = (const float*)d_in[11];
    const float* b2  = (const float*)d_in[12];
    const float* g1  = (const float*)d_in[13];
    const float* be1 = (const float*)d_in[14];
    const float* g2  = (const float*)d_in[15];
    const float* be2 = (const float*)d_in[16];
    float* out = (float*)d_out;

    __half *h, *qkv, *attnh, *ffh, *wqkv, *wo, *w1, *w2, *x1h;
    float *bqkv;
    cudaGetSymbolAddress((void**)&h,     g_h);
    cudaGetSymbolAddress((void**)&qkv,   g_qkv);
    cudaGetSymbolAddress((void**)&attnh, g_attnh);
    cudaGetSymbolAddress((void**)&x1h,   g_x1h);
    cudaGetSymbolAddress((void**)&ffh,   g_ffh);
    cudaGetSymbolAddress((void**)&wqkv,  g_wqkv);
    cudaGetSymbolAddress((void**)&wo,    g_wo);
    cudaGetSymbolAddress((void**)&w1,    g_w1);
    cudaGetSymbolAddress((void**)&w2,    g_w2);
    cudaGetSymbolAddress((void**)&bqkv,  g_bqkv);

    cudaFuncSetAttribute(gemm16_kernel<false,false,false,true>,
                         cudaFuncAttributeMaxDynamicSharedMemorySize, GSMEM);
    cudaFuncSetAttribute(gemm16_kernel<false,true,false,true>,
                         cudaFuncAttributeMaxDynamicSharedMemorySize, GSMEM);
    cudaFuncSetAttribute(gemm16_kernel<true,false,false,true>,
                         cudaFuncAttributeMaxDynamicSharedMemorySize, GSMEM);
    cudaFuncSetAttribute(gemm16_kernel<false,true,true,false>,
                         cudaFuncAttributeMaxDynamicSharedMemorySize, GSMEM);

    {
        dim3 g(256, 7);   // y=0..5 weights, y=6 bias concat
        f2h_all_kernel<<<g, 256>>>(Wq, Wk, Wv, Wo, W1, W2, bq, bk, bv,
                                   wqkv, wo, w1, w2, bqkv);
    }

    // 1) h = LN1(x) -> fp16
    ln_kernel<<<N_NODES / 16, 512>>>(x, g1, be1, h);

    // 2) qkv = h @ Wqkv^T + bqkv (fp16 out)
    dim3 grdQKV(QKVDIM / BN, N_NODES / BM);   // (12, 512)
    gemm16_kernel<false,false,false,true><<<grdQKV, 256, GSMEM>>>(h, wqkv, bqkv, nullptr, qkv, EMBED, QKVDIM);

    // 3) per-node attention -> fp16
    attn_kernel<<<N_NODES / 8, 256>>>(qkv, attnh);

    // 4) x1h = x + attnh @ Wo^T + bo (fp16 out, fp32 residual in)
    dim3 grdE(EMBED / BN, N_NODES / BM);      // (4, 512)
    gemm16_kernel<false,true,false,true><<<grdE, 256, GSMEM>>>(attnh, wo, bo, x, x1h, EMBED, EMBED);

    // 5) h = LN2(x1h) -> fp16
    ln_h_kernel<<<N_NODES / 16, 512>>>(x1h, g2, be2, h);

    // 6) ffh = relu(h @ W1^T + b1) -> fp16
    dim3 grdF(FFDIM / BN, N_NODES / BM);      // (16, 512)
    gemm16_kernel<true,false,false,true><<<grdF, 256, GSMEM>>>(h, w1, b1, nullptr, ffh, EMBED, FFDIM);

    // 7) out = x1h + ffh @ W2^T + b2 (fp32 out, fp16 residual in)
    gemm16_kernel<false,true,true,false><<<grdE, 256, GSMEM>>>(ffh, w2, b2, x1h, out, FFDIM, EMBED);
}